// round 8
// baseline (speedup 1.0000x reference)
#include <cuda_runtime.h>
#include <math.h>

#define BB 16
#define DD 8
#define FF 2
#define EE 10
#define EP 12          // padded row (float4-aligned, 48B)
#define NP 512
#define NPAIR 36
#define LOG2E 1.4426950408889634f

// ---------------- scratch (device globals; no allocation allowed) ----------
__device__ float g_Sigma[BB][EE][EE];
__device__ float g_nu[BB][NP][EE];
__device__ float g_Pp[BB][DD][NP][EP];       // padded P
__device__ float g_logk[BB][DD][NP];
__device__ float g_mu_delta[BB][DD];
__device__ float g_V[BB][DD][EE];
__device__ float g_Tlp[BB][NPAIR][NP][EP];   // (Pa @ S) * log2(e), padded
__device__ float g_gv[BB][NPAIR][NP];
__device__ float g_hv[BB][NPAIR][NP];
__device__ float g_g2[BB][NPAIR][NP];
__device__ float g_h2[BB][NPAIR][NP];
__device__ float g_EDD[BB][DD][DD];
__device__ float g_tr[BB][DD];

__device__ __forceinline__ float ex2f(float x) {
    float y;
    asm("ex2.approx.ftz.f32 %0, %1;" : "=f"(y) : "f"(x));
    return y;
}
__device__ __forceinline__ unsigned long long pk2(float lo, float hi) {
    unsigned long long r;
    asm("mov.b64 %0, {%1, %2};" : "=l"(r) : "f"(lo), "f"(hi));
    return r;
}
__device__ __forceinline__ unsigned long long fma2(unsigned long long a, unsigned long long b,
                                                   unsigned long long c) {
    unsigned long long r;
    asm("fma.rn.f32x2 %0, %1, %2, %3;" : "=l"(r) : "l"(a), "l"(b), "l"(c));
    return r;
}
__device__ __forceinline__ float hsum2(unsigned long long v) {
    float lo, hi;
    asm("mov.b64 {%0, %1}, %2;" : "=f"(lo), "=f"(hi) : "l"(v));
    return lo + hi;
}

__device__ __forceinline__ void pair_of(int p, int &a, int &d) {
    int aa = 0;
    while (p >= DD - aa) { p -= DD - aa; aa++; }
    a = aa; d = aa + p;
}

__device__ float blockReduceSum(float v, float* sred) {
    const unsigned full = 0xffffffffu;
    #pragma unroll
    for (int o = 16; o > 0; o >>= 1) v += __shfl_down_sync(full, v, o);
    int t = threadIdx.x, warp = t >> 5, lane = t & 31;
    int nw = blockDim.x >> 5;
    if (lane == 0) sred[warp] = v;
    __syncthreads();
    float r = (t < nw) ? sred[t] : 0.f;
    if (warp == 0) {
        #pragma unroll
        for (int o = 16; o > 0; o >>= 1) r += __shfl_down_sync(full, r, o);
        if (lane == 0) sred[0] = r;
    }
    __syncthreads();
    float out = sred[0];
    __syncthreads();
    return out;
}

// Gauss-Jordan in shared memory; warp 0 cooperates, lanes = columns.
__device__ void gj_solve10(float (*M)[EE + 1], float (*X)[EE + 1], float* ldout) {
    int t = threadIdx.x;
    if (t < 32) {
        int lane = t;
        float ld = 0.f;
        for (int k = 0; k < EE; k++) {
            float piv = M[k][k];
            ld += logf(fabsf(piv));
            float inv = 1.f / piv;
            __syncwarp();
            if (lane < EE) { M[k][lane] *= inv; X[k][lane] *= inv; }
            __syncwarp();
            for (int r = 0; r < EE; r++) {
                if (r == k) continue;
                float fac = M[r][k];
                __syncwarp();
                if (lane < EE) {
                    M[r][lane] -= fac * M[k][lane];
                    X[r][lane] -= fac * X[k][lane];
                }
                __syncwarp();
            }
        }
        if (lane == 0) *ldout = ld;
    }
    __syncthreads();
}

// ---------------- kernel 1: mu, Sigma, nu, P, logk -------------------------
__global__ void __launch_bounds__(NP)
k_prep(const float* __restrict__ obs_mean, const float* __restrict__ obs_var,
       const float* __restrict__ action_mean, const float* __restrict__ action_var,
       const float* __restrict__ cross_cov, const float* __restrict__ X_train,
       const float* __restrict__ ell, const float* __restrict__ alpha_sq) {
    int b = blockIdx.x, t = threadIdx.x;
    __shared__ float smu[EE];
    __shared__ float siLam[DD][EE];
    __shared__ float slal[DD];
    if (t < DD) smu[t] = obs_mean[b * DD + t];
    else if (t < EE) smu[t] = action_mean[b * FF + (t - DD)];
    if (t < DD * EE) {
        int d = t / EE, e = t % EE;
        float l = ell[d * EE + e];
        siLam[d][e] = 1.f / (l * l);
    }
    if (t >= 128 && t < 128 + DD) slal[t - 128] = logf(alpha_sq[t - 128]);
    if (t >= 256 && t < 256 + EE * EE) {
        int q = t - 256, e = q / EE, f = q % EE;
        float v;
        if (e < DD && f < DD)      v = obs_var[b * DD * DD + e * DD + f];
        else if (e < DD)           v = cross_cov[b * DD * FF + e * FF + (f - DD)];
        else if (f < DD)           v = cross_cov[b * DD * FF + f * FF + (e - DD)];
        else                       v = action_var[b * FF * FF + (e - DD) * FF + (f - DD)];
        g_Sigma[b][e][f] = v;
    }
    __syncthreads();
    int n = t;
    float nu[EE];
    #pragma unroll
    for (int e = 0; e < EE; e++) {
        nu[e] = X_train[n * EE + e] - smu[e];
        g_nu[b][n][e] = nu[e];
    }
    for (int d = 0; d < DD; d++) {
        float s = 0.f;
        #pragma unroll
        for (int e = 0; e < EE; e++) {
            float p = nu[e] * siLam[d][e];
            g_Pp[b][d][n][e] = p;
            s = fmaf(nu[e] * nu[e], siLam[d][e], s);
        }
        g_Pp[b][d][n][10] = 0.f;
        g_Pp[b][d][n][11] = 0.f;
        g_logk[b][d][n] = slal[d] - 0.5f * s;
    }
}

// ---------------- kernel 2: per (b,d) -- Ainv, q, mu_delta, w, V -----------
__global__ void __launch_bounds__(NP)
k_perdim(const float* __restrict__ ell, const float* __restrict__ alpha_sq,
         const float* __restrict__ beta) {
    int bd = blockIdx.x;
    int b = bd / DD, d = bd % DD;
    int t = threadIdx.x;
    __shared__ float sM[EE][EE + 1], sX[EE][EE + 1];
    __shared__ float sld;
    __shared__ float sred[32];
    if (t < EE * EE) {
        int e = t / EE, f = t % EE;
        float diag = (e == f) ? (ell[d * EE + e] * ell[d * EE + e]) : 0.f;
        sM[e][f] = g_Sigma[b][e][f] + diag;
        sX[e][f] = (e == f) ? 1.f : 0.f;
    }
    __syncthreads();
    gj_solve10(sM, sX, &sld);

    float ldl = 0.f;
    #pragma unroll
    for (int e = 0; e < EE; e++) { float l = ell[d * EE + e]; ldl += logf(l * l); }

    int n = t;
    float nu[EE];
    #pragma unroll
    for (int e = 0; e < EE; e++) nu[e] = g_nu[b][n][e];
    float quad = 0.f;
    #pragma unroll
    for (int e = 0; e < EE; e++) {
        float acc = 0.f;
        #pragma unroll
        for (int f = 0; f < EE; f++) acc = fmaf(sX[e][f], nu[f], acc);
        quad = fmaf(nu[e], acc, quad);
    }
    float q = alpha_sq[d] * __expf(0.5f * (ldl - sld) - 0.5f * quad);
    float bq = beta[d * NP + n] * q;

    float md = blockReduceSum(bq, sred);
    float wreg[EE];
    for (int e = 0; e < EE; e++) wreg[e] = blockReduceSum(bq * nu[e], sred);

    if (t == 0) {
        g_mu_delta[b][d] = md;
        float u[EE];
        for (int e = 0; e < EE; e++) {
            float a = 0.f;
            for (int f = 0; f < EE; f++) a = fmaf(sX[e][f], wreg[f], a);
            u[e] = a;
        }
        for (int e = 0; e < EE; e++) {
            float a = 0.f;
            for (int f = 0; f < EE; f++) a = fmaf(g_Sigma[b][e][f], u[f], a);
            g_V[b][d][e] = a;
        }
    }
}

// ---------------- kernel 3: per (b,pair) -- S, logdetR, T, g, h ------------
__global__ void __launch_bounds__(NP)
k_pairprep(const float* __restrict__ ell, const float* __restrict__ beta) {
    int bp = blockIdx.x;
    int b = bp / NPAIR, p = bp % NPAIR;
    int a, d;
    pair_of(p, a, d);
    int t = threadIdx.x;
    __shared__ float sM[EE][EE + 1], sX[EE][EE + 1];
    __shared__ float sld;
    if (t < EE * EE) {
        int e = t / EE, f = t % EE;
        float la = ell[a * EE + f], ldd = ell[d * EE + f];
        float ils = 1.f / (la * la) + 1.f / (ldd * ldd);
        sM[e][f] = g_Sigma[b][e][f] * ils + ((e == f) ? 1.f : 0.f);
        sX[e][f] = g_Sigma[b][e][f];
    }
    __syncthreads();
    gj_solve10(sM, sX, &sld);  // sX = S, sld = logdetR

    int n = t;
    float Pv[EE], Tv[EE];
    #pragma unroll
    for (int e = 0; e < EE; e++) Pv[e] = g_Pp[b][a][n][e];
    #pragma unroll
    for (int e = 0; e < EE; e++) {
        float acc = 0.f;
        #pragma unroll
        for (int f = 0; f < EE; f++) acc = fmaf(Pv[f], sX[f][e], acc);
        Tv[e] = acc;
    }
    float da = 0.f;
    #pragma unroll
    for (int e = 0; e < EE; e++) da = fmaf(Tv[e], Pv[e], da);
    #pragma unroll
    for (int e = 0; e < EE; e++) g_Tlp[b][p][n][e] = Tv[e] * LOG2E;
    g_Tlp[b][p][n][10] = 0.f;
    g_Tlp[b][p][n][11] = 0.f;
    float g2 = __expf(g_logk[b][a][n] + 0.5f * da - 0.25f * sld);
    g_g2[b][p][n] = g2;
    g_gv[b][p][n] = beta[a * NP + n] * g2;
    #pragma unroll
    for (int e = 0; e < EE; e++) Pv[e] = g_Pp[b][d][n][e];
    #pragma unroll
    for (int e = 0; e < EE; e++) {
        float acc = 0.f;
        #pragma unroll
        for (int f = 0; f < EE; f++) acc = fmaf(Pv[f], sX[f][e], acc);
        Tv[e] = acc;
    }
    float db = 0.f;
    #pragma unroll
    for (int e = 0; e < EE; e++) db = fmaf(Tv[e], Pv[e], db);
    float h2 = __expf(g_logk[b][d][n] + 0.5f * db - 0.25f * sld);
    g_h2[b][p][n] = h2;
    g_hv[b][p][n] = beta[d * NP + n] * h2;
}

// ---------------- kernel 4: the big 512x512 contractions -------------------
// f32x2 packed dot products + vectorized smem tiles.
__global__ void __launch_bounds__(256) k_main(const float* __restrict__ invK) {
    int bp = blockIdx.x;
    int b = bp / NPAIR, p = bp % NPAIR;
    int a, d;
    pair_of(p, a, d);
    const bool diag = (a == d);
    int t = threadIdx.x, tx = t & 15, ty = t >> 4;

    __shared__ __align__(16) float sT[64][EP];
    __shared__ __align__(16) float sP[64][EP];
    __shared__ float sg[64], sh[64], sg2[64], sh2[64];
    __shared__ float sred[32];

    const float* Krow = invK + (size_t)a * NP * NP;

    float acc = 0.f, tacc = 0.f;

    for (int i0 = 0; i0 < NP; i0 += 64) {
        {
            const float4* srcT = (const float4*)&g_Tlp[b][p][i0][0];
            float4* dstT = (float4*)&sT[0][0];
            for (int k = t; k < 64 * EP / 4; k += 256) dstT[k] = srcT[k];
            for (int k = t; k < 64; k += 256) {
                sg[k] = g_gv[b][p][i0 + k];
                sg2[k] = g_g2[b][p][i0 + k];
            }
        }
        __syncthreads();

        // pack T rows for this thread's 4 i-rows into f32x2 pairs
        unsigned long long Tp[4][5];
        #pragma unroll
        for (int ii = 0; ii < 4; ii++) {
            int r = ty * 4 + ii;
            #pragma unroll
            for (int k = 0; k < 5; k++) Tp[ii][k] = pk2(sT[r][2 * k], sT[r][2 * k + 1]);
        }

        float racc[4] = {0.f, 0.f, 0.f, 0.f};
        float t2acc[4] = {0.f, 0.f, 0.f, 0.f};

        for (int j0 = 0; j0 < NP; j0 += 64) {
            {
                const float4* srcP = (const float4*)&g_Pp[b][d][j0][0];
                float4* dstP = (float4*)&sP[0][0];
                for (int k = t; k < 64 * EP / 4; k += 256) dstP[k] = srcP[k];
                for (int k = t; k < 64; k += 256) {
                    sh[k] = g_hv[b][p][j0 + k];
                    sh2[k] = g_h2[b][p][j0 + k];
                }
            }
            __syncthreads();

            if (diag) {
                float kvv[4][4];
                #pragma unroll
                for (int ii = 0; ii < 4; ii++) {
                    const float4 kv4 = *(const float4*)(Krow + (size_t)(i0 + ty * 4 + ii) * NP + j0 + tx * 4);
                    kvv[ii][0] = kv4.x; kvv[ii][1] = kv4.y; kvv[ii][2] = kv4.z; kvv[ii][3] = kv4.w;
                }
                #pragma unroll
                for (int jj = 0; jj < 4; jj++) {
                    int r = tx * 4 + jj;
                    const float4 q0 = *(const float4*)&sP[r][0];
                    const float4 q1 = *(const float4*)&sP[r][4];
                    const float2 q2 = *(const float2*)&sP[r][8];
                    unsigned long long P0 = pk2(q0.x, q0.y), P1 = pk2(q0.z, q0.w);
                    unsigned long long P2 = pk2(q1.x, q1.y), P3 = pk2(q1.z, q1.w);
                    unsigned long long P4 = pk2(q2.x, q2.y);
                    float hj = sh[r], h2j = sh2[r];
                    float e2v[4];
                    #pragma unroll
                    for (int ii = 0; ii < 4; ii++) {
                        unsigned long long m2 = fma2(Tp[ii][0], P0, 0ull);
                        m2 = fma2(Tp[ii][1], P1, m2);
                        m2 = fma2(Tp[ii][2], P2, m2);
                        m2 = fma2(Tp[ii][3], P3, m2);
                        m2 = fma2(Tp[ii][4], P4, m2);
                        e2v[ii] = ex2f(hsum2(m2));
                    }
                    #pragma unroll
                    for (int ii = 0; ii < 4; ii++) {
                        racc[ii] = fmaf(e2v[ii], hj, racc[ii]);
                        t2acc[ii] = fmaf(e2v[ii] * h2j, kvv[ii][jj], t2acc[ii]);
                    }
                }
            } else {
                #pragma unroll
                for (int jj = 0; jj < 4; jj++) {
                    int r = tx * 4 + jj;
                    const float4 q0 = *(const float4*)&sP[r][0];
                    const float4 q1 = *(const float4*)&sP[r][4];
                    const float2 q2 = *(const float2*)&sP[r][8];
                    unsigned long long P0 = pk2(q0.x, q0.y), P1 = pk2(q0.z, q0.w);
                    unsigned long long P2 = pk2(q1.x, q1.y), P3 = pk2(q1.z, q1.w);
                    unsigned long long P4 = pk2(q2.x, q2.y);
                    float hj = sh[r];
                    #pragma unroll
                    for (int ii = 0; ii < 4; ii++) {
                        unsigned long long m2 = fma2(Tp[ii][0], P0, 0ull);
                        m2 = fma2(Tp[ii][1], P1, m2);
                        m2 = fma2(Tp[ii][2], P2, m2);
                        m2 = fma2(Tp[ii][3], P3, m2);
                        m2 = fma2(Tp[ii][4], P4, m2);
                        racc[ii] = fmaf(ex2f(hsum2(m2)), hj, racc[ii]);
                    }
                }
            }
            __syncthreads();
        }

        #pragma unroll
        for (int ii = 0; ii < 4; ii++) {
            int r = ty * 4 + ii;
            acc = fmaf(sg[r], racc[ii], acc);
            if (diag) tacc = fmaf(sg2[r], t2acc[ii], tacc);
        }
        __syncthreads();
    }

    float tot = blockReduceSum(acc, sred);
    if (diag) {
        float tt = blockReduceSum(tacc, sred);
        if (t == 0) g_tr[b][a] = tt;
    }
    if (t == 0) {
        g_EDD[b][a][d] = tot;
        g_EDD[b][d][a] = tot;
    }
}

// ---------------- kernel 5: final assembly ---------------------------------
__global__ void __launch_bounds__(64)
k_final(const float* __restrict__ obs_mean, const float* __restrict__ obs_var,
        const float* __restrict__ alpha_sq, const float* __restrict__ sigma_sq_eps,
        float* __restrict__ out) {
    int b = blockIdx.x, t = threadIdx.x;
    if (t < DD) {
        out[b * DD + t] = obs_mean[b * DD + t] + g_mu_delta[b][t];
    }
    if (t < DD * DD) {
        int i = t / DD, j = t % DD;
        float sd = g_EDD[b][i][j] - g_mu_delta[b][i] * g_mu_delta[b][j];
        if (i == j) sd += alpha_sq[i] - g_tr[b][i] + sigma_sq_eps[i];
        float v = obs_var[b * DD * DD + i * DD + j] + sd + g_V[b][j][i] + g_V[b][i][j];
        out[BB * DD + b * DD * DD + i * DD + j] = v;
    }
}

extern "C" void kernel_launch(void* const* d_in, const int* in_sizes, int n_in,
                              void* d_out, int out_size) {
    const float* obs_mean     = (const float*)d_in[0];
    const float* obs_var      = (const float*)d_in[1];
    const float* action_mean  = (const float*)d_in[2];
    const float* action_var   = (const float*)d_in[3];
    const float* cross_cov    = (const float*)d_in[4];
    const float* X_train      = (const float*)d_in[5];
    const float* ell          = (const float*)d_in[6];
    const float* alpha_sq     = (const float*)d_in[7];
    const float* sigma_sq_eps = (const float*)d_in[8];
    const float* beta         = (const float*)d_in[9];
    const float* inv_K        = (const float*)d_in[10];
    float* out = (float*)d_out;

    k_prep<<<BB, NP>>>(obs_mean, obs_var, action_mean, action_var, cross_cov,
                       X_train, ell, alpha_sq);
    k_perdim<<<BB * DD, NP>>>(ell, alpha_sq, beta);
    k_pairprep<<<BB * NPAIR, NP>>>(ell, beta);
    k_main<<<BB * NPAIR, 256>>>(inv_K);
    k_final<<<BB, 64>>>(obs_mean, obs_var, alpha_sq, sigma_sq_eps, out);
}

// round 10
// speedup vs baseline: 1.4346x; 1.4346x over previous
#include <cuda_runtime.h>
#include <math.h>

#define BB 16
#define DD 8
#define FF 2
#define EE 10
#define EP 12          // padded row (float4-aligned, 48B)
#define NP 512
#define NPAIR 36
#define NOFF 28
#define LOG2E 1.4426950408889634f

// ---------------- scratch (device globals; no allocation allowed) ----------
__device__ float g_Sigma[BB][EE][EE];
__device__ float g_nu[BB][NP][EE];
__device__ float g_Pp[BB][DD][NP][EP];       // padded P
__device__ float g_logk[BB][DD][NP];
__device__ float g_mu_delta[BB][DD];
__device__ float g_V[BB][DD][EE];
__device__ float g_Tlp[BB][NPAIR][NP][EP];   // (Pa @ S) * log2(e), padded
__device__ float g_gv[BB][NPAIR][NP];
__device__ float g_hv[BB][NPAIR][NP];
__device__ float g_g2[BB][NPAIR][NP];
__device__ float g_h2[BB][NPAIR][NP];
__device__ float g_EDD[BB][DD][DD];
__device__ float g_tr[BB][DD];

__device__ __forceinline__ float ex2f(float x) {
    float y;
    asm("ex2.approx.ftz.f32 %0, %1;" : "=f"(y) : "f"(x));
    return y;
}

__device__ __forceinline__ void pair_of(int p, int &a, int &d) {
    int aa = 0;
    while (p >= DD - aa) { p -= DD - aa; aa++; }
    a = aa; d = aa + p;
}
__device__ __forceinline__ void pair_off(int p, int &a, int &d) {
    int aa = 0;
    while (p >= DD - 1 - aa) { p -= DD - 1 - aa; aa++; }
    a = aa; d = aa + 1 + p;
}
// index of (a,d), a<=d, in pair_of enumeration
__device__ __forceinline__ int pfull(int a, int d) {
    return a * (2 * DD - a + 1) / 2 + (d - a);
}

__device__ float blockReduceSum(float v, float* sred) {
    const unsigned full = 0xffffffffu;
    #pragma unroll
    for (int o = 16; o > 0; o >>= 1) v += __shfl_down_sync(full, v, o);
    int t = threadIdx.x, warp = t >> 5, lane = t & 31;
    int nw = blockDim.x >> 5;
    if (lane == 0) sred[warp] = v;
    __syncthreads();
    float r = (t < nw) ? sred[t] : 0.f;
    if (warp == 0) {
        #pragma unroll
        for (int o = 16; o > 0; o >>= 1) r += __shfl_down_sync(full, r, o);
        if (lane == 0) sred[0] = r;
    }
    __syncthreads();
    float out = sred[0];
    __syncthreads();
    return out;
}

// Gauss-Jordan in shared memory; warp 0 cooperates, lanes = columns.
__device__ void gj_solve10(float (*M)[EE + 1], float (*X)[EE + 1], float* ldout) {
    int t = threadIdx.x;
    if (t < 32) {
        int lane = t;
        float ld = 0.f;
        for (int k = 0; k < EE; k++) {
            float piv = M[k][k];
            ld += logf(fabsf(piv));
            float inv = 1.f / piv;
            __syncwarp();
            if (lane < EE) { M[k][lane] *= inv; X[k][lane] *= inv; }
            __syncwarp();
            for (int r = 0; r < EE; r++) {
                if (r == k) continue;
                float fac = M[r][k];
                __syncwarp();
                if (lane < EE) {
                    M[r][lane] -= fac * M[k][lane];
                    X[r][lane] -= fac * X[k][lane];
                }
                __syncwarp();
            }
        }
        if (lane == 0) *ldout = ld;
    }
    __syncthreads();
}

// ---------------- kernel 1: mu, Sigma, nu, P, logk -------------------------
__global__ void __launch_bounds__(NP)
k_prep(const float* __restrict__ obs_mean, const float* __restrict__ obs_var,
       const float* __restrict__ action_mean, const float* __restrict__ action_var,
       const float* __restrict__ cross_cov, const float* __restrict__ X_train,
       const float* __restrict__ ell, const float* __restrict__ alpha_sq) {
    int b = blockIdx.x, t = threadIdx.x;
    __shared__ float smu[EE];
    __shared__ float siLam[DD][EE];
    __shared__ float slal[DD];
    if (t < DD) smu[t] = obs_mean[b * DD + t];
    else if (t < EE) smu[t] = action_mean[b * FF + (t - DD)];
    if (t < DD * EE) {
        int d = t / EE, e = t % EE;
        float l = ell[d * EE + e];
        siLam[d][e] = 1.f / (l * l);
    }
    if (t >= 128 && t < 128 + DD) slal[t - 128] = logf(alpha_sq[t - 128]);
    if (t >= 256 && t < 256 + EE * EE) {
        int q = t - 256, e = q / EE, f = q % EE;
        float v;
        if (e < DD && f < DD)      v = obs_var[b * DD * DD + e * DD + f];
        else if (e < DD)           v = cross_cov[b * DD * FF + e * FF + (f - DD)];
        else if (f < DD)           v = cross_cov[b * DD * FF + f * FF + (e - DD)];
        else                       v = action_var[b * FF * FF + (e - DD) * FF + (f - DD)];
        g_Sigma[b][e][f] = v;
    }
    __syncthreads();
    int n = t;
    float nu[EE];
    #pragma unroll
    for (int e = 0; e < EE; e++) {
        nu[e] = X_train[n * EE + e] - smu[e];
        g_nu[b][n][e] = nu[e];
    }
    for (int d = 0; d < DD; d++) {
        float s = 0.f;
        #pragma unroll
        for (int e = 0; e < EE; e++) {
            float p = nu[e] * siLam[d][e];
            g_Pp[b][d][n][e] = p;
            s = fmaf(nu[e] * nu[e], siLam[d][e], s);
        }
        g_Pp[b][d][n][10] = 0.f;
        g_Pp[b][d][n][11] = 0.f;
        g_logk[b][d][n] = slal[d] - 0.5f * s;
    }
}

// ---------------- kernel 2: per (b,d) -- Ainv, q, mu_delta, w, V -----------
__global__ void __launch_bounds__(NP)
k_perdim(const float* __restrict__ ell, const float* __restrict__ alpha_sq,
         const float* __restrict__ beta) {
    int bd = blockIdx.x;
    int b = bd / DD, d = bd % DD;
    int t = threadIdx.x;
    __shared__ float sM[EE][EE + 1], sX[EE][EE + 1];
    __shared__ float sld;
    __shared__ float sred[32];
    if (t < EE * EE) {
        int e = t / EE, f = t % EE;
        float diag = (e == f) ? (ell[d * EE + e] * ell[d * EE + e]) : 0.f;
        sM[e][f] = g_Sigma[b][e][f] + diag;
        sX[e][f] = (e == f) ? 1.f : 0.f;
    }
    __syncthreads();
    gj_solve10(sM, sX, &sld);

    float ldl = 0.f;
    #pragma unroll
    for (int e = 0; e < EE; e++) { float l = ell[d * EE + e]; ldl += logf(l * l); }

    int n = t;
    float nu[EE];
    #pragma unroll
    for (int e = 0; e < EE; e++) nu[e] = g_nu[b][n][e];
    float quad = 0.f;
    #pragma unroll
    for (int e = 0; e < EE; e++) {
        float acc = 0.f;
        #pragma unroll
        for (int f = 0; f < EE; f++) acc = fmaf(sX[e][f], nu[f], acc);
        quad = fmaf(nu[e], acc, quad);
    }
    float q = alpha_sq[d] * __expf(0.5f * (ldl - sld) - 0.5f * quad);
    float bq = beta[d * NP + n] * q;

    float md = blockReduceSum(bq, sred);
    float wreg[EE];
    for (int e = 0; e < EE; e++) wreg[e] = blockReduceSum(bq * nu[e], sred);

    if (t == 0) {
        g_mu_delta[b][d] = md;
        float u[EE];
        for (int e = 0; e < EE; e++) {
            float a = 0.f;
            for (int f = 0; f < EE; f++) a = fmaf(sX[e][f], wreg[f], a);
            u[e] = a;
        }
        for (int e = 0; e < EE; e++) {
            float a = 0.f;
            for (int f = 0; f < EE; f++) a = fmaf(g_Sigma[b][e][f], u[f], a);
            g_V[b][d][e] = a;
        }
    }
}

// ---------------- kernel 3: per (b,pair) -- S, logdetR, T, g, h ------------
__global__ void __launch_bounds__(NP)
k_pairprep(const float* __restrict__ ell, const float* __restrict__ beta) {
    int bp = blockIdx.x;
    int b = bp / NPAIR, p = bp % NPAIR;
    int a, d;
    pair_of(p, a, d);
    int t = threadIdx.x;
    __shared__ float sM[EE][EE + 1], sX[EE][EE + 1];
    __shared__ float sld;
    if (t < EE * EE) {
        int e = t / EE, f = t % EE;
        float la = ell[a * EE + f], ldd = ell[d * EE + f];
        float ils = 1.f / (la * la) + 1.f / (ldd * ldd);
        sM[e][f] = g_Sigma[b][e][f] * ils + ((e == f) ? 1.f : 0.f);
        sX[e][f] = g_Sigma[b][e][f];
    }
    __syncthreads();
    gj_solve10(sM, sX, &sld);  // sX = S, sld = logdetR

    int n = t;
    float Pv[EE], Tv[EE];
    #pragma unroll
    for (int e = 0; e < EE; e++) Pv[e] = g_Pp[b][a][n][e];
    #pragma unroll
    for (int e = 0; e < EE; e++) {
        float acc = 0.f;
        #pragma unroll
        for (int f = 0; f < EE; f++) acc = fmaf(Pv[f], sX[f][e], acc);
        Tv[e] = acc;
    }
    float da = 0.f;
    #pragma unroll
    for (int e = 0; e < EE; e++) da = fmaf(Tv[e], Pv[e], da);
    #pragma unroll
    for (int e = 0; e < EE; e++) g_Tlp[b][p][n][e] = Tv[e] * LOG2E;
    g_Tlp[b][p][n][10] = 0.f;
    g_Tlp[b][p][n][11] = 0.f;
    float g2 = __expf(g_logk[b][a][n] + 0.5f * da - 0.25f * sld);
    g_g2[b][p][n] = g2;
    g_gv[b][p][n] = beta[a * NP + n] * g2;
    #pragma unroll
    for (int e = 0; e < EE; e++) Pv[e] = g_Pp[b][d][n][e];
    #pragma unroll
    for (int e = 0; e < EE; e++) {
        float acc = 0.f;
        #pragma unroll
        for (int f = 0; f < EE; f++) acc = fmaf(Pv[f], sX[f][e], acc);
        Tv[e] = acc;
    }
    float db = 0.f;
    #pragma unroll
    for (int e = 0; e < EE; e++) db = fmaf(Tv[e], Pv[e], db);
    float h2 = __expf(g_logk[b][d][n] + 0.5f * db - 0.25f * sld);
    g_h2[b][p][n] = h2;
    g_hv[b][p][n] = beta[d * NP + n] * h2;
}

// ---------------- kernel 4a: off-diagonal pairs (a<d), register-lean -------
__global__ void __launch_bounds__(256, 3) k_main_off() {
    int bp = blockIdx.x;
    int b = bp / NOFF, p28 = bp % NOFF;
    int a, d;
    pair_off(p28, a, d);
    int p = pfull(a, d);
    int t = threadIdx.x, tx = t & 15, ty = t >> 4;

    __shared__ __align__(16) float sT[64][EP];
    __shared__ __align__(16) float sP[64][EP];
    __shared__ float sg[64], sh[64];
    __shared__ float sred[32];

    float acc = 0.f;

    for (int i0 = 0; i0 < NP; i0 += 64) {
        {
            const float4* srcT = (const float4*)&g_Tlp[b][p][i0][0];
            float4* dstT = (float4*)&sT[0][0];
            for (int k = t; k < 64 * EP / 4; k += 256) dstT[k] = srcT[k];
            if (t < 64) sg[t] = g_gv[b][p][i0 + t];
        }
        __syncthreads();

        float Treg[4][EE];
        #pragma unroll
        for (int ii = 0; ii < 4; ii++) {
            int r = ty * 4 + ii;
            const float4 w0 = *(const float4*)&sT[r][0];
            const float4 w1 = *(const float4*)&sT[r][4];
            const float2 w2 = *(const float2*)&sT[r][8];
            Treg[ii][0] = w0.x; Treg[ii][1] = w0.y; Treg[ii][2] = w0.z; Treg[ii][3] = w0.w;
            Treg[ii][4] = w1.x; Treg[ii][5] = w1.y; Treg[ii][6] = w1.z; Treg[ii][7] = w1.w;
            Treg[ii][8] = w2.x; Treg[ii][9] = w2.y;
        }

        float racc[4] = {0.f, 0.f, 0.f, 0.f};

        for (int j0 = 0; j0 < NP; j0 += 64) {
            {
                const float4* srcP = (const float4*)&g_Pp[b][d][j0][0];
                float4* dstP = (float4*)&sP[0][0];
                for (int k = t; k < 64 * EP / 4; k += 256) dstP[k] = srcP[k];
                if (t < 64) sh[t] = g_hv[b][p][j0 + t];
            }
            __syncthreads();

            #pragma unroll
            for (int jj = 0; jj < 4; jj++) {
                int r = tx * 4 + jj;
                const float4 q0 = *(const float4*)&sP[r][0];
                const float4 q1 = *(const float4*)&sP[r][4];
                const float2 q2 = *(const float2*)&sP[r][8];
                float Pv[EE];
                Pv[0] = q0.x; Pv[1] = q0.y; Pv[2] = q0.z; Pv[3] = q0.w;
                Pv[4] = q1.x; Pv[5] = q1.y; Pv[6] = q1.z; Pv[7] = q1.w;
                Pv[8] = q2.x; Pv[9] = q2.y;
                float hj = sh[r];
                float m0 = 0.f, m1 = 0.f, m2 = 0.f, m3 = 0.f;
                #pragma unroll
                for (int e = 0; e < EE; e++) {
                    m0 = fmaf(Treg[0][e], Pv[e], m0);
                    m1 = fmaf(Treg[1][e], Pv[e], m1);
                    m2 = fmaf(Treg[2][e], Pv[e], m2);
                    m3 = fmaf(Treg[3][e], Pv[e], m3);
                }
                racc[0] = fmaf(ex2f(m0), hj, racc[0]);
                racc[1] = fmaf(ex2f(m1), hj, racc[1]);
                racc[2] = fmaf(ex2f(m2), hj, racc[2]);
                racc[3] = fmaf(ex2f(m3), hj, racc[3]);
            }
            __syncthreads();
        }

        #pragma unroll
        for (int ii = 0; ii < 4; ii++) acc = fmaf(sg[ty * 4 + ii], racc[ii], acc);
        __syncthreads();
    }

    float tot = blockReduceSum(acc, sred);
    if (t == 0) {
        g_EDD[b][a][d] = tot;
        g_EDD[b][d][a] = tot;
    }
}

// ---------------- kernel 4b: diagonal pairs (a==d), 2x4 micro-tile ---------
__global__ void __launch_bounds__(256, 3) k_main_diag(const float* __restrict__ invK) {
    int bp = blockIdx.x;
    int b = bp / DD, a = bp % DD;
    int p = pfull(a, a);
    int t = threadIdx.x, tx = t & 15, ty = t >> 4;   // ty in 0..15 -> 32 i-rows per tile

    __shared__ __align__(16) float sT[32][EP];
    __shared__ __align__(16) float sP[64][EP];
    __shared__ float sg[32], sh[64], sg2[32], sh2[64];
    __shared__ float sred[32];

    const float* Krow = invK + (size_t)a * NP * NP;

    float acc = 0.f, tacc = 0.f;

    for (int i0 = 0; i0 < NP; i0 += 32) {
        {
            const float4* srcT = (const float4*)&g_Tlp[b][p][i0][0];
            float4* dstT = (float4*)&sT[0][0];
            for (int k = t; k < 32 * EP / 4; k += 256) dstT[k] = srcT[k];
            if (t < 32) {
                sg[t] = g_gv[b][p][i0 + t];
                sg2[t] = g_g2[b][p][i0 + t];
            }
        }
        __syncthreads();

        float Treg[2][EE];
        #pragma unroll
        for (int ii = 0; ii < 2; ii++) {
            int r = ty * 2 + ii;
            const float4 w0 = *(const float4*)&sT[r][0];
            const float4 w1 = *(const float4*)&sT[r][4];
            const float2 w2 = *(const float2*)&sT[r][8];
            Treg[ii][0] = w0.x; Treg[ii][1] = w0.y; Treg[ii][2] = w0.z; Treg[ii][3] = w0.w;
            Treg[ii][4] = w1.x; Treg[ii][5] = w1.y; Treg[ii][6] = w1.z; Treg[ii][7] = w1.w;
            Treg[ii][8] = w2.x; Treg[ii][9] = w2.y;
        }

        float racc[2] = {0.f, 0.f};
        float t2acc[2] = {0.f, 0.f};

        for (int j0 = 0; j0 < NP; j0 += 64) {
            {
                const float4* srcP = (const float4*)&g_Pp[b][a][j0][0];
                float4* dstP = (float4*)&sP[0][0];
                for (int k = t; k < 64 * EP / 4; k += 256) dstP[k] = srcP[k];
                if (t < 64) {
                    sh[t] = g_hv[b][p][j0 + t];
                    sh2[t] = g_h2[b][p][j0 + t];
                }
            }
            __syncthreads();

            float kvv[2][4];
            #pragma unroll
            for (int ii = 0; ii < 2; ii++) {
                const float4 kv4 = *(const float4*)(Krow + (size_t)(i0 + ty * 2 + ii) * NP + j0 + tx * 4);
                kvv[ii][0] = kv4.x; kvv[ii][1] = kv4.y; kvv[ii][2] = kv4.z; kvv[ii][3] = kv4.w;
            }

            #pragma unroll
            for (int jj = 0; jj < 4; jj++) {
                int r = tx * 4 + jj;
                const float4 q0 = *(const float4*)&sP[r][0];
                const float4 q1 = *(const float4*)&sP[r][4];
                const float2 q2 = *(const float2*)&sP[r][8];
                float Pv[EE];
                Pv[0] = q0.x; Pv[1] = q0.y; Pv[2] = q0.z; Pv[3] = q0.w;
                Pv[4] = q1.x; Pv[5] = q1.y; Pv[6] = q1.z; Pv[7] = q1.w;
                Pv[8] = q2.x; Pv[9] = q2.y;
                float hj = sh[r], h2j = sh2[r];
                float m0 = 0.f, m1 = 0.f;
                #pragma unroll
                for (int e = 0; e < EE; e++) {
                    m0 = fmaf(Treg[0][e], Pv[e], m0);
                    m1 = fmaf(Treg[1][e], Pv[e], m1);
                }
                float e0 = ex2f(m0), e1 = ex2f(m1);
                racc[0] = fmaf(e0, hj, racc[0]);
                racc[1] = fmaf(e1, hj, racc[1]);
                t2acc[0] = fmaf(e0 * h2j, kvv[0][jj], t2acc[0]);
                t2acc[1] = fmaf(e1 * h2j, kvv[1][jj], t2acc[1]);
            }
            __syncthreads();
        }

        #pragma unroll
        for (int ii = 0; ii < 2; ii++) {
            int r = ty * 2 + ii;
            acc = fmaf(sg[r], racc[ii], acc);
            tacc = fmaf(sg2[r], t2acc[ii], tacc);
        }
        __syncthreads();
    }

    float tot = blockReduceSum(acc, sred);
    float tt = blockReduceSum(tacc, sred);
    if (t == 0) {
        g_EDD[b][a][a] = tot;
        g_tr[b][a] = tt;
    }
}

// ---------------- kernel 5: final assembly ---------------------------------
__global__ void __launch_bounds__(64)
k_final(const float* __restrict__ obs_mean, const float* __restrict__ obs_var,
        const float* __restrict__ alpha_sq, const float* __restrict__ sigma_sq_eps,
        float* __restrict__ out) {
    int b = blockIdx.x, t = threadIdx.x;
    if (t < DD) {
        out[b * DD + t] = obs_mean[b * DD + t] + g_mu_delta[b][t];
    }
    if (t < DD * DD) {
        int i = t / DD, j = t % DD;
        float sd = g_EDD[b][i][j] - g_mu_delta[b][i] * g_mu_delta[b][j];
        if (i == j) sd += alpha_sq[i] - g_tr[b][i] + sigma_sq_eps[i];
        float v = obs_var[b * DD * DD + i * DD + j] + sd + g_V[b][j][i] + g_V[b][i][j];
        out[BB * DD + b * DD * DD + i * DD + j] = v;
    }
}

extern "C" void kernel_launch(void* const* d_in, const int* in_sizes, int n_in,
                              void* d_out, int out_size) {
    const float* obs_mean     = (const float*)d_in[0];
    const float* obs_var      = (const float*)d_in[1];
    const float* action_mean  = (const float*)d_in[2];
    const float* action_var   = (const float*)d_in[3];
    const float* cross_cov    = (const float*)d_in[4];
    const float* X_train      = (const float*)d_in[5];
    const float* ell          = (const float*)d_in[6];
    const float* alpha_sq     = (const float*)d_in[7];
    const float* sigma_sq_eps = (const float*)d_in[8];
    const float* beta         = (const float*)d_in[9];
    const float* inv_K        = (const float*)d_in[10];
    float* out = (float*)d_out;

    k_prep<<<BB, NP>>>(obs_mean, obs_var, action_mean, action_var, cross_cov,
                       X_train, ell, alpha_sq);
    k_perdim<<<BB * DD, NP>>>(ell, alpha_sq, beta);
    k_pairprep<<<BB * NPAIR, NP>>>(ell, beta);
    k_main_off<<<BB * NOFF, 256>>>();
    k_main_diag<<<BB * DD, 256>>>(inv_K);
    k_final<<<BB, 64>>>(obs_mean, obs_var, alpha_sq, sigma_sq_eps, out);
}

// round 11
// speedup vs baseline: 2.3897x; 1.6658x over previous
#include <cuda_runtime.h>
#include <math.h>

#define BB 16
#define DD 8
#define FF 2
#define EE 10
#define EP 12          // padded row (float4-aligned, 48B = 3x16B, odd multiple of 16)
#define NP 512
#define NPAIR 36
#define NOFF 28
#define LOG2E 1.4426950408889634f

// ---------------- scratch (device globals; no allocation allowed) ----------
__device__ float g_Sigma[BB][EE][EE];
__device__ float g_nu[BB][NP][EE];
__device__ float g_Pp[BB][DD][NP][EP];       // padded P
__device__ float g_logk[BB][DD][NP];
__device__ float g_mu_delta[BB][DD];
__device__ float g_V[BB][DD][EE];
__device__ float g_Tlp[BB][NPAIR][NP][EP];   // (Pa @ S) * log2(e), padded
__device__ float g_gv[BB][NPAIR][NP];
__device__ float g_hv[BB][NPAIR][NP];
__device__ float g_g2[BB][NPAIR][NP];
__device__ float g_h2[BB][NPAIR][NP];
__device__ float g_EDD[BB][DD][DD];
__device__ float g_tr[BB][DD];

__device__ __forceinline__ float ex2f(float x) {
    float y;
    asm("ex2.approx.ftz.f32 %0, %1;" : "=f"(y) : "f"(x));
    return y;
}

__device__ __forceinline__ void pair_of(int p, int &a, int &d) {
    int aa = 0;
    while (p >= DD - aa) { p -= DD - aa; aa++; }
    a = aa; d = aa + p;
}
__device__ __forceinline__ void pair_off(int p, int &a, int &d) {
    int aa = 0;
    while (p >= DD - 1 - aa) { p -= DD - 1 - aa; aa++; }
    a = aa; d = aa + 1 + p;
}
// index of (a,d), a<=d, in pair_of enumeration
__device__ __forceinline__ int pfull(int a, int d) {
    return a * (2 * DD - a + 1) / 2 + (d - a);
}

__device__ float blockReduceSum(float v, float* sred) {
    const unsigned full = 0xffffffffu;
    #pragma unroll
    for (int o = 16; o > 0; o >>= 1) v += __shfl_down_sync(full, v, o);
    int t = threadIdx.x, warp = t >> 5, lane = t & 31;
    int nw = blockDim.x >> 5;
    if (lane == 0) sred[warp] = v;
    __syncthreads();
    float r = (t < nw) ? sred[t] : 0.f;
    if (warp == 0) {
        #pragma unroll
        for (int o = 16; o > 0; o >>= 1) r += __shfl_down_sync(full, r, o);
        if (lane == 0) sred[0] = r;
    }
    __syncthreads();
    float out = sred[0];
    __syncthreads();
    return out;
}

// Gauss-Jordan in shared memory; warp 0 cooperates, lanes = columns.
__device__ void gj_solve10(float (*M)[EE + 1], float (*X)[EE + 1], float* ldout) {
    int t = threadIdx.x;
    if (t < 32) {
        int lane = t;
        float ld = 0.f;
        for (int k = 0; k < EE; k++) {
            float piv = M[k][k];
            ld += logf(fabsf(piv));
            float inv = 1.f / piv;
            __syncwarp();
            if (lane < EE) { M[k][lane] *= inv; X[k][lane] *= inv; }
            __syncwarp();
            for (int r = 0; r < EE; r++) {
                if (r == k) continue;
                float fac = M[r][k];
                __syncwarp();
                if (lane < EE) {
                    M[r][lane] -= fac * M[k][lane];
                    X[r][lane] -= fac * X[k][lane];
                }
                __syncwarp();
            }
        }
        if (lane == 0) *ldout = ld;
    }
    __syncthreads();
}

// ---------------- kernel 1: mu, Sigma, nu, P, logk -------------------------
__global__ void __launch_bounds__(NP)
k_prep(const float* __restrict__ obs_mean, const float* __restrict__ obs_var,
       const float* __restrict__ action_mean, const float* __restrict__ action_var,
       const float* __restrict__ cross_cov, const float* __restrict__ X_train,
       const float* __restrict__ ell, const float* __restrict__ alpha_sq) {
    int b = blockIdx.x, t = threadIdx.x;
    __shared__ float smu[EE];
    __shared__ float siLam[DD][EE];
    __shared__ float slal[DD];
    if (t < DD) smu[t] = obs_mean[b * DD + t];
    else if (t < EE) smu[t] = action_mean[b * FF + (t - DD)];
    if (t < DD * EE) {
        int d = t / EE, e = t % EE;
        float l = ell[d * EE + e];
        siLam[d][e] = 1.f / (l * l);
    }
    if (t >= 128 && t < 128 + DD) slal[t - 128] = logf(alpha_sq[t - 128]);
    if (t >= 256 && t < 256 + EE * EE) {
        int q = t - 256, e = q / EE, f = q % EE;
        float v;
        if (e < DD && f < DD)      v = obs_var[b * DD * DD + e * DD + f];
        else if (e < DD)           v = cross_cov[b * DD * FF + e * FF + (f - DD)];
        else if (f < DD)           v = cross_cov[b * DD * FF + f * FF + (e - DD)];
        else                       v = action_var[b * FF * FF + (e - DD) * FF + (f - DD)];
        g_Sigma[b][e][f] = v;
    }
    __syncthreads();
    int n = t;
    float nu[EE];
    #pragma unroll
    for (int e = 0; e < EE; e++) {
        nu[e] = X_train[n * EE + e] - smu[e];
        g_nu[b][n][e] = nu[e];
    }
    for (int d = 0; d < DD; d++) {
        float s = 0.f;
        #pragma unroll
        for (int e = 0; e < EE; e++) {
            float p = nu[e] * siLam[d][e];
            g_Pp[b][d][n][e] = p;
            s = fmaf(nu[e] * nu[e], siLam[d][e], s);
        }
        g_Pp[b][d][n][10] = 0.f;
        g_Pp[b][d][n][11] = 0.f;
        g_logk[b][d][n] = slal[d] - 0.5f * s;
    }
}

// ---------------- kernel 2: per (b,d) -- Ainv, q, mu_delta, w, V -----------
__global__ void __launch_bounds__(NP)
k_perdim(const float* __restrict__ ell, const float* __restrict__ alpha_sq,
         const float* __restrict__ beta) {
    int bd = blockIdx.x;
    int b = bd / DD, d = bd % DD;
    int t = threadIdx.x;
    __shared__ float sM[EE][EE + 1], sX[EE][EE + 1];
    __shared__ float sld;
    __shared__ float sred[32];
    if (t < EE * EE) {
        int e = t / EE, f = t % EE;
        float diag = (e == f) ? (ell[d * EE + e] * ell[d * EE + e]) : 0.f;
        sM[e][f] = g_Sigma[b][e][f] + diag;
        sX[e][f] = (e == f) ? 1.f : 0.f;
    }
    __syncthreads();
    gj_solve10(sM, sX, &sld);

    float ldl = 0.f;
    #pragma unroll
    for (int e = 0; e < EE; e++) { float l = ell[d * EE + e]; ldl += logf(l * l); }

    int n = t;
    float nu[EE];
    #pragma unroll
    for (int e = 0; e < EE; e++) nu[e] = g_nu[b][n][e];
    float quad = 0.f;
    #pragma unroll
    for (int e = 0; e < EE; e++) {
        float acc = 0.f;
        #pragma unroll
        for (int f = 0; f < EE; f++) acc = fmaf(sX[e][f], nu[f], acc);
        quad = fmaf(nu[e], acc, quad);
    }
    float q = alpha_sq[d] * __expf(0.5f * (ldl - sld) - 0.5f * quad);
    float bq = beta[d * NP + n] * q;

    float md = blockReduceSum(bq, sred);
    float wreg[EE];
    for (int e = 0; e < EE; e++) wreg[e] = blockReduceSum(bq * nu[e], sred);

    if (t == 0) {
        g_mu_delta[b][d] = md;
        float u[EE];
        for (int e = 0; e < EE; e++) {
            float a = 0.f;
            for (int f = 0; f < EE; f++) a = fmaf(sX[e][f], wreg[f], a);
            u[e] = a;
        }
        for (int e = 0; e < EE; e++) {
            float a = 0.f;
            for (int f = 0; f < EE; f++) a = fmaf(g_Sigma[b][e][f], u[f], a);
            g_V[b][d][e] = a;
        }
    }
}

// ---------------- kernel 3: per (b,pair) -- S, logdetR, T, g, h ------------
__global__ void __launch_bounds__(NP)
k_pairprep(const float* __restrict__ ell, const float* __restrict__ beta) {
    int bp = blockIdx.x;
    int b = bp / NPAIR, p = bp % NPAIR;
    int a, d;
    pair_of(p, a, d);
    int t = threadIdx.x;
    __shared__ float sM[EE][EE + 1], sX[EE][EE + 1];
    __shared__ float sld;
    if (t < EE * EE) {
        int e = t / EE, f = t % EE;
        float la = ell[a * EE + f], ldd = ell[d * EE + f];
        float ils = 1.f / (la * la) + 1.f / (ldd * ldd);
        sM[e][f] = g_Sigma[b][e][f] * ils + ((e == f) ? 1.f : 0.f);
        sX[e][f] = g_Sigma[b][e][f];
    }
    __syncthreads();
    gj_solve10(sM, sX, &sld);  // sX = S, sld = logdetR

    int n = t;
    float Pv[EE], Tv[EE];
    #pragma unroll
    for (int e = 0; e < EE; e++) Pv[e] = g_Pp[b][a][n][e];
    #pragma unroll
    for (int e = 0; e < EE; e++) {
        float acc = 0.f;
        #pragma unroll
        for (int f = 0; f < EE; f++) acc = fmaf(Pv[f], sX[f][e], acc);
        Tv[e] = acc;
    }
    float da = 0.f;
    #pragma unroll
    for (int e = 0; e < EE; e++) da = fmaf(Tv[e], Pv[e], da);
    #pragma unroll
    for (int e = 0; e < EE; e++) g_Tlp[b][p][n][e] = Tv[e] * LOG2E;
    g_Tlp[b][p][n][10] = 0.f;
    g_Tlp[b][p][n][11] = 0.f;
    float g2 = __expf(g_logk[b][a][n] + 0.5f * da - 0.25f * sld);
    g_g2[b][p][n] = g2;
    g_gv[b][p][n] = beta[a * NP + n] * g2;
    #pragma unroll
    for (int e = 0; e < EE; e++) Pv[e] = g_Pp[b][d][n][e];
    #pragma unroll
    for (int e = 0; e < EE; e++) {
        float acc = 0.f;
        #pragma unroll
        for (int f = 0; f < EE; f++) acc = fmaf(Pv[f], sX[f][e], acc);
        Tv[e] = acc;
    }
    float db = 0.f;
    #pragma unroll
    for (int e = 0; e < EE; e++) db = fmaf(Tv[e], Pv[e], db);
    float h2 = __expf(g_logk[b][d][n] + 0.5f * db - 0.25f * sld);
    g_h2[b][p][n] = h2;
    g_hv[b][p][n] = beta[d * NP + n] * h2;
}

// ---------------- kernel 4a: off-diagonal pairs (a<d) ----------------------
// Cyclic micro-tile mapping: lane handles rows {k*16 + lane_idx} so that
// consecutive lanes read consecutive smem rows (stride 48B = 3x16B) -> LDS.128
// runs at its 2-phase floor instead of 8-way bank conflicts.
__global__ void __launch_bounds__(256, 3) k_main_off() {
    int bp = blockIdx.x;
    int b = bp / NOFF, p28 = bp % NOFF;
    int a, d;
    pair_off(p28, a, d);
    int p = pfull(a, d);
    int t = threadIdx.x, tx = t & 15, ty = t >> 4;

    __shared__ __align__(16) float sT[64][EP];
    __shared__ __align__(16) float sP[64][EP];
    __shared__ float sg[64], sh[64];
    __shared__ float sred[32];

    float acc = 0.f;

    for (int i0 = 0; i0 < NP; i0 += 64) {
        {
            const float4* srcT = (const float4*)&g_Tlp[b][p][i0][0];
            float4* dstT = (float4*)&sT[0][0];
            for (int k = t; k < 64 * EP / 4; k += 256) dstT[k] = srcT[k];
            if (t < 64) sg[t] = g_gv[b][p][i0 + t];
        }
        __syncthreads();

        float Treg[4][EE];
        #pragma unroll
        for (int ii = 0; ii < 4; ii++) {
            int r = ii * 16 + ty;
            const float4 w0 = *(const float4*)&sT[r][0];
            const float4 w1 = *(const float4*)&sT[r][4];
            const float2 w2 = *(const float2*)&sT[r][8];
            Treg[ii][0] = w0.x; Treg[ii][1] = w0.y; Treg[ii][2] = w0.z; Treg[ii][3] = w0.w;
            Treg[ii][4] = w1.x; Treg[ii][5] = w1.y; Treg[ii][6] = w1.z; Treg[ii][7] = w1.w;
            Treg[ii][8] = w2.x; Treg[ii][9] = w2.y;
        }

        float racc[4] = {0.f, 0.f, 0.f, 0.f};

        for (int j0 = 0; j0 < NP; j0 += 64) {
            {
                const float4* srcP = (const float4*)&g_Pp[b][d][j0][0];
                float4* dstP = (float4*)&sP[0][0];
                for (int k = t; k < 64 * EP / 4; k += 256) dstP[k] = srcP[k];
                if (t < 64) sh[t] = g_hv[b][p][j0 + t];
            }
            __syncthreads();

            #pragma unroll
            for (int jj = 0; jj < 4; jj++) {
                int r = jj * 16 + tx;
                const float4 q0 = *(const float4*)&sP[r][0];
                const float4 q1 = *(const float4*)&sP[r][4];
                const float2 q2 = *(const float2*)&sP[r][8];
                float Pv[EE];
                Pv[0] = q0.x; Pv[1] = q0.y; Pv[2] = q0.z; Pv[3] = q0.w;
                Pv[4] = q1.x; Pv[5] = q1.y; Pv[6] = q1.z; Pv[7] = q1.w;
                Pv[8] = q2.x; Pv[9] = q2.y;
                float hj = sh[r];
                float m0 = 0.f, m1 = 0.f, m2 = 0.f, m3 = 0.f;
                #pragma unroll
                for (int e = 0; e < EE; e++) {
                    m0 = fmaf(Treg[0][e], Pv[e], m0);
                    m1 = fmaf(Treg[1][e], Pv[e], m1);
                    m2 = fmaf(Treg[2][e], Pv[e], m2);
                    m3 = fmaf(Treg[3][e], Pv[e], m3);
                }
                racc[0] = fmaf(ex2f(m0), hj, racc[0]);
                racc[1] = fmaf(ex2f(m1), hj, racc[1]);
                racc[2] = fmaf(ex2f(m2), hj, racc[2]);
                racc[3] = fmaf(ex2f(m3), hj, racc[3]);
            }
            __syncthreads();
        }

        #pragma unroll
        for (int ii = 0; ii < 4; ii++) acc = fmaf(sg[ii * 16 + ty], racc[ii], acc);
        __syncthreads();
    }

    float tot = blockReduceSum(acc, sred);
    if (t == 0) {
        g_EDD[b][a][d] = tot;
        g_EDD[b][d][a] = tot;
    }
}

// ---------------- kernel 4b: diagonal pairs (a==d), 2x4 cyclic tile --------
__global__ void __launch_bounds__(256, 3) k_main_diag(const float* __restrict__ invK) {
    int bp = blockIdx.x;
    int b = bp / DD, a = bp % DD;
    int p = pfull(a, a);
    int t = threadIdx.x, tx = t & 15, ty = t >> 4;

    __shared__ __align__(16) float sT[32][EP];
    __shared__ __align__(16) float sP[64][EP];
    __shared__ float sg[32], sh[64], sg2[32], sh2[64];
    __shared__ float sred[32];

    const float* Krow = invK + (size_t)a * NP * NP;

    float acc = 0.f, tacc = 0.f;

    for (int i0 = 0; i0 < NP; i0 += 32) {
        {
            const float4* srcT = (const float4*)&g_Tlp[b][p][i0][0];
            float4* dstT = (float4*)&sT[0][0];
            for (int k = t; k < 32 * EP / 4; k += 256) dstT[k] = srcT[k];
            if (t < 32) {
                sg[t] = g_gv[b][p][i0 + t];
                sg2[t] = g_g2[b][p][i0 + t];
            }
        }
        __syncthreads();

        float Treg[2][EE];
        #pragma unroll
        for (int ii = 0; ii < 2; ii++) {
            int r = ii * 16 + ty;   // rows ty and 16+ty
            const float4 w0 = *(const float4*)&sT[r][0];
            const float4 w1 = *(const float4*)&sT[r][4];
            const float2 w2 = *(const float2*)&sT[r][8];
            Treg[ii][0] = w0.x; Treg[ii][1] = w0.y; Treg[ii][2] = w0.z; Treg[ii][3] = w0.w;
            Treg[ii][4] = w1.x; Treg[ii][5] = w1.y; Treg[ii][6] = w1.z; Treg[ii][7] = w1.w;
            Treg[ii][8] = w2.x; Treg[ii][9] = w2.y;
        }

        float racc[2] = {0.f, 0.f};
        float t2acc[2] = {0.f, 0.f};

        for (int j0 = 0; j0 < NP; j0 += 64) {
            {
                const float4* srcP = (const float4*)&g_Pp[b][a][j0][0];
                float4* dstP = (float4*)&sP[0][0];
                for (int k = t; k < 64 * EP / 4; k += 256) dstP[k] = srcP[k];
                if (t < 64) {
                    sh[t] = g_hv[b][p][j0 + t];
                    sh2[t] = g_h2[b][p][j0 + t];
                }
            }
            __syncthreads();

            #pragma unroll
            for (int jj = 0; jj < 4; jj++) {
                int r = jj * 16 + tx;
                const float4 q0 = *(const float4*)&sP[r][0];
                const float4 q1 = *(const float4*)&sP[r][4];
                const float2 q2 = *(const float2*)&sP[r][8];
                float Pv[EE];
                Pv[0] = q0.x; Pv[1] = q0.y; Pv[2] = q0.z; Pv[3] = q0.w;
                Pv[4] = q1.x; Pv[5] = q1.y; Pv[6] = q1.z; Pv[7] = q1.w;
                Pv[8] = q2.x; Pv[9] = q2.y;
                float hj = sh[r], h2j = sh2[r];
                float k0 = Krow[(size_t)(i0 + ty) * NP + j0 + r];
                float k1 = Krow[(size_t)(i0 + 16 + ty) * NP + j0 + r];
                float m0 = 0.f, m1 = 0.f;
                #pragma unroll
                for (int e = 0; e < EE; e++) {
                    m0 = fmaf(Treg[0][e], Pv[e], m0);
                    m1 = fmaf(Treg[1][e], Pv[e], m1);
                }
                float e0 = ex2f(m0), e1 = ex2f(m1);
                racc[0] = fmaf(e0, hj, racc[0]);
                racc[1] = fmaf(e1, hj, racc[1]);
                t2acc[0] = fmaf(e0 * h2j, k0, t2acc[0]);
                t2acc[1] = fmaf(e1 * h2j, k1, t2acc[1]);
            }
            __syncthreads();
        }

        #pragma unroll
        for (int ii = 0; ii < 2; ii++) {
            int r = ii * 16 + ty;
            acc = fmaf(sg[r], racc[ii], acc);
            tacc = fmaf(sg2[r], t2acc[ii], tacc);
        }
        __syncthreads();
    }

    float tot = blockReduceSum(acc, sred);
    float tt = blockReduceSum(tacc, sred);
    if (t == 0) {
        g_EDD[b][a][a] = tot;
        g_tr[b][a] = tt;
    }
}

// ---------------- kernel 5: final assembly ---------------------------------
__global__ void __launch_bounds__(64)
k_final(const float* __restrict__ obs_mean, const float* __restrict__ obs_var,
        const float* __restrict__ alpha_sq, const float* __restrict__ sigma_sq_eps,
        float* __restrict__ out) {
    int b = blockIdx.x, t = threadIdx.x;
    if (t < DD) {
        out[b * DD + t] = obs_mean[b * DD + t] + g_mu_delta[b][t];
    }
    if (t < DD * DD) {
        int i = t / DD, j = t % DD;
        float sd = g_EDD[b][i][j] - g_mu_delta[b][i] * g_mu_delta[b][j];
        if (i == j) sd += alpha_sq[i] - g_tr[b][i] + sigma_sq_eps[i];
        float v = obs_var[b * DD * DD + i * DD + j] + sd + g_V[b][j][i] + g_V[b][i][j];
        out[BB * DD + b * DD * DD + i * DD + j] = v;
    }
}

extern "C" void kernel_launch(void* const* d_in, const int* in_sizes, int n_in,
                              void* d_out, int out_size) {
    const float* obs_mean     = (const float*)d_in[0];
    const float* obs_var      = (const float*)d_in[1];
    const float* action_mean  = (const float*)d_in[2];
    const float* action_var   = (const float*)d_in[3];
    const float* cross_cov    = (const float*)d_in[4];
    const float* X_train      = (const float*)d_in[5];
    const float* ell          = (const float*)d_in[6];
    const float* alpha_sq     = (const float*)d_in[7];
    const float* sigma_sq_eps = (const float*)d_in[8];
    const float* beta         = (const float*)d_in[9];
    const float* inv_K        = (const float*)d_in[10];
    float* out = (float*)d_out;

    k_prep<<<BB, NP>>>(obs_mean, obs_var, action_mean, action_var, cross_cov,
                       X_train, ell, alpha_sq);
    k_perdim<<<BB * DD, NP>>>(ell, alpha_sq, beta);
    k_pairprep<<<BB * NPAIR, NP>>>(ell, beta);
    k_main_off<<<BB * NOFF, 256>>>();
    k_main_diag<<<BB * DD, 256>>>(inv_K);
    k_final<<<BB, 64>>>(obs_mean, obs_var, alpha_sq, sigma_sq_eps, out);
}

// round 13
// speedup vs baseline: 2.5948x; 1.0858x over previous
#include <cuda_runtime.h>
#include <math.h>

#define BB 16
#define DD 8
#define FF 2
#define EE 10
#define EP 12          // padded row (float4-aligned, 48B = 3x16B, odd multiple of 16)
#define NP 512
#define NPAIR 36
#define NOFF 28
#define NCHUNK 4       // i-chunks for the diagonal kernel
#define LOG2E 1.4426950408889634f

// ---------------- scratch (device globals; no allocation allowed) ----------
__device__ float g_Sigma[BB][EE][EE];
__device__ float g_nu[BB][NP][EE];
__device__ float g_Pp[BB][DD][NP][EP];       // padded P
__device__ float g_logk[BB][DD][NP];
__device__ float g_mu_delta[BB][DD];
__device__ float g_V[BB][DD][EE];
__device__ float g_Tlp[BB][NPAIR][NP][EP];   // (Pa @ S) * log2(e), padded
__device__ float g_gv[BB][NPAIR][NP];
__device__ float g_hv[BB][NPAIR][NP];
__device__ float g_g2[BB][NPAIR][NP];
__device__ float g_h2[BB][NPAIR][NP];
__device__ float g_EDD[BB][DD][DD];
__device__ float g_EDDd[NCHUNK][BB][DD];     // diag partials per i-chunk
__device__ float g_trp[NCHUNK][BB][DD];      // trace partials per i-chunk

__device__ __forceinline__ float ex2f(float x) {
    float y;
    asm("ex2.approx.ftz.f32 %0, %1;" : "=f"(y) : "f"(x));
    return y;
}

__device__ __forceinline__ void pair_of(int p, int &a, int &d) {
    int aa = 0;
    while (p >= DD - aa) { p -= DD - aa; aa++; }
    a = aa; d = aa + p;
}
__device__ __forceinline__ void pair_off(int p, int &a, int &d) {
    int aa = 0;
    while (p >= DD - 1 - aa) { p -= DD - 1 - aa; aa++; }
    a = aa; d = aa + 1 + p;
}
// index of (a,d), a<=d, in pair_of enumeration
__device__ __forceinline__ int pfull(int a, int d) {
    return a * (2 * DD - a + 1) / 2 + (d - a);
}

__device__ float blockReduceSum(float v, float* sred) {
    const unsigned full = 0xffffffffu;
    #pragma unroll
    for (int o = 16; o > 0; o >>= 1) v += __shfl_down_sync(full, v, o);
    int t = threadIdx.x, warp = t >> 5, lane = t & 31;
    int nw = blockDim.x >> 5;
    if (lane == 0) sred[warp] = v;
    __syncthreads();
    float r = (t < nw) ? sred[t] : 0.f;
    if (warp == 0) {
        #pragma unroll
        for (int o = 16; o > 0; o >>= 1) r += __shfl_down_sync(full, r, o);
        if (lane == 0) sred[0] = r;
    }
    __syncthreads();
    float out = sred[0];
    __syncthreads();
    return out;
}

// Gauss-Jordan in shared memory; warp 0 cooperates, lanes = columns.
__device__ void gj_solve10(float (*M)[EE + 1], float (*X)[EE + 1], float* ldout) {
    int t = threadIdx.x;
    if (t < 32) {
        int lane = t;
        float ld = 0.f;
        for (int k = 0; k < EE; k++) {
            float piv = M[k][k];
            ld += logf(fabsf(piv));
            float inv = 1.f / piv;
            __syncwarp();
            if (lane < EE) { M[k][lane] *= inv; X[k][lane] *= inv; }
            __syncwarp();
            for (int r = 0; r < EE; r++) {
                if (r == k) continue;
                float fac = M[r][k];
                __syncwarp();
                if (lane < EE) {
                    M[r][lane] -= fac * M[k][lane];
                    X[r][lane] -= fac * X[k][lane];
                }
                __syncwarp();
            }
        }
        if (lane == 0) *ldout = ld;
    }
    __syncthreads();
}

// ---------------- kernel 1: mu, Sigma, nu, P, logk -------------------------
__global__ void __launch_bounds__(NP)
k_prep(const float* __restrict__ obs_mean, const float* __restrict__ obs_var,
       const float* __restrict__ action_mean, const float* __restrict__ action_var,
       const float* __restrict__ cross_cov, const float* __restrict__ X_train,
       const float* __restrict__ ell, const float* __restrict__ alpha_sq) {
    int b = blockIdx.x, t = threadIdx.x;
    __shared__ float smu[EE];
    __shared__ float siLam[DD][EE];
    __shared__ float slal[DD];
    if (t < DD) smu[t] = obs_mean[b * DD + t];
    else if (t < EE) smu[t] = action_mean[b * FF + (t - DD)];
    if (t < DD * EE) {
        int d = t / EE, e = t % EE;
        float l = ell[d * EE + e];
        siLam[d][e] = 1.f / (l * l);
    }
    if (t >= 128 && t < 128 + DD) slal[t - 128] = logf(alpha_sq[t - 128]);
    if (t >= 256 && t < 256 + EE * EE) {
        int q = t - 256, e = q / EE, f = q % EE;
        float v;
        if (e < DD && f < DD)      v = obs_var[b * DD * DD + e * DD + f];
        else if (e < DD)           v = cross_cov[b * DD * FF + e * FF + (f - DD)];
        else if (f < DD)           v = cross_cov[b * DD * FF + f * FF + (e - DD)];
        else                       v = action_var[b * FF * FF + (e - DD) * FF + (f - DD)];
        g_Sigma[b][e][f] = v;
    }
    __syncthreads();
    int n = t;
    float nu[EE];
    #pragma unroll
    for (int e = 0; e < EE; e++) {
        nu[e] = X_train[n * EE + e] - smu[e];
        g_nu[b][n][e] = nu[e];
    }
    for (int d = 0; d < DD; d++) {
        float s = 0.f;
        #pragma unroll
        for (int e = 0; e < EE; e++) {
            float p = nu[e] * siLam[d][e];
            g_Pp[b][d][n][e] = p;
            s = fmaf(nu[e] * nu[e], siLam[d][e], s);
        }
        g_Pp[b][d][n][10] = 0.f;
        g_Pp[b][d][n][11] = 0.f;
        g_logk[b][d][n] = slal[d] - 0.5f * s;
    }
}

// ---------------- kernel 2: per (b,d) -- Ainv, q, mu_delta, w, V -----------
__global__ void __launch_bounds__(NP)
k_perdim(const float* __restrict__ ell, const float* __restrict__ alpha_sq,
         const float* __restrict__ beta) {
    int bd = blockIdx.x;
    int b = bd / DD, d = bd % DD;
    int t = threadIdx.x;
    __shared__ float sM[EE][EE + 1], sX[EE][EE + 1];
    __shared__ float sld;
    __shared__ float sred[32];
    if (t < EE * EE) {
        int e = t / EE, f = t % EE;
        float diag = (e == f) ? (ell[d * EE + e] * ell[d * EE + e]) : 0.f;
        sM[e][f] = g_Sigma[b][e][f] + diag;
        sX[e][f] = (e == f) ? 1.f : 0.f;
    }
    __syncthreads();
    gj_solve10(sM, sX, &sld);

    float ldl = 0.f;
    #pragma unroll
    for (int e = 0; e < EE; e++) { float l = ell[d * EE + e]; ldl += logf(l * l); }

    int n = t;
    float nu[EE];
    #pragma unroll
    for (int e = 0; e < EE; e++) nu[e] = g_nu[b][n][e];
    float quad = 0.f;
    #pragma unroll
    for (int e = 0; e < EE; e++) {
        float acc = 0.f;
        #pragma unroll
        for (int f = 0; f < EE; f++) acc = fmaf(sX[e][f], nu[f], acc);
        quad = fmaf(nu[e], acc, quad);
    }
    float q = alpha_sq[d] * __expf(0.5f * (ldl - sld) - 0.5f * quad);
    float bq = beta[d * NP + n] * q;

    float md = blockReduceSum(bq, sred);
    float wreg[EE];
    for (int e = 0; e < EE; e++) wreg[e] = blockReduceSum(bq * nu[e], sred);

    if (t == 0) {
        g_mu_delta[b][d] = md;
        float u[EE];
        for (int e = 0; e < EE; e++) {
            float a = 0.f;
            for (int f = 0; f < EE; f++) a = fmaf(sX[e][f], wreg[f], a);
            u[e] = a;
        }
        for (int e = 0; e < EE; e++) {
            float a = 0.f;
            for (int f = 0; f < EE; f++) a = fmaf(g_Sigma[b][e][f], u[f], a);
            g_V[b][d][e] = a;
        }
    }
}

// ---------------- kernel 3: per (b,pair) -- S, logdetR, T, g, h ------------
__global__ void __launch_bounds__(NP)
k_pairprep(const float* __restrict__ ell, const float* __restrict__ beta) {
    int bp = blockIdx.x;
    int b = bp / NPAIR, p = bp % NPAIR;
    int a, d;
    pair_of(p, a, d);
    int t = threadIdx.x;
    __shared__ float sM[EE][EE + 1], sX[EE][EE + 1];
    __shared__ float sld;
    if (t < EE * EE) {
        int e = t / EE, f = t % EE;
        float la = ell[a * EE + f], ldd = ell[d * EE + f];
        float ils = 1.f / (la * la) + 1.f / (ldd * ldd);
        sM[e][f] = g_Sigma[b][e][f] * ils + ((e == f) ? 1.f : 0.f);
        sX[e][f] = g_Sigma[b][e][f];
    }
    __syncthreads();
    gj_solve10(sM, sX, &sld);  // sX = S, sld = logdetR

    int n = t;
    float Pv[EE], Tv[EE];
    #pragma unroll
    for (int e = 0; e < EE; e++) Pv[e] = g_Pp[b][a][n][e];
    #pragma unroll
    for (int e = 0; e < EE; e++) {
        float acc = 0.f;
        #pragma unroll
        for (int f = 0; f < EE; f++) acc = fmaf(Pv[f], sX[f][e], acc);
        Tv[e] = acc;
    }
    float da = 0.f;
    #pragma unroll
    for (int e = 0; e < EE; e++) da = fmaf(Tv[e], Pv[e], da);
    #pragma unroll
    for (int e = 0; e < EE; e++) g_Tlp[b][p][n][e] = Tv[e] * LOG2E;
    g_Tlp[b][p][n][10] = 0.f;
    g_Tlp[b][p][n][11] = 0.f;
    float g2 = __expf(g_logk[b][a][n] + 0.5f * da - 0.25f * sld);
    g_g2[b][p][n] = g2;
    g_gv[b][p][n] = beta[a * NP + n] * g2;
    #pragma unroll
    for (int e = 0; e < EE; e++) Pv[e] = g_Pp[b][d][n][e];
    #pragma unroll
    for (int e = 0; e < EE; e++) {
        float acc = 0.f;
        #pragma unroll
        for (int f = 0; f < EE; f++) acc = fmaf(Pv[f], sX[f][e], acc);
        Tv[e] = acc;
    }
    float db = 0.f;
    #pragma unroll
    for (int e = 0; e < EE; e++) db = fmaf(Tv[e], Pv[e], db);
    float h2 = __expf(g_logk[b][d][n] + 0.5f * db - 0.25f * sld);
    g_h2[b][p][n] = h2;
    g_hv[b][p][n] = beta[d * NP + n] * h2;
}

// ---------------- kernel 4a: off-diagonal pairs (a<d) ----------------------
// Cyclic micro-tile mapping (conflict-free LDS). At the FMA roofline; unchanged.
__global__ void __launch_bounds__(256, 3) k_main_off() {
    int bp = blockIdx.x;
    int b = bp / NOFF, p28 = bp % NOFF;
    int a, d;
    pair_off(p28, a, d);
    int p = pfull(a, d);
    int t = threadIdx.x, tx = t & 15, ty = t >> 4;

    __shared__ __align__(16) float sT[64][EP];
    __shared__ __align__(16) float sP[64][EP];
    __shared__ float sg[64], sh[64];
    __shared__ float sred[32];

    float acc = 0.f;

    for (int i0 = 0; i0 < NP; i0 += 64) {
        {
            const float4* srcT = (const float4*)&g_Tlp[b][p][i0][0];
            float4* dstT = (float4*)&sT[0][0];
            for (int k = t; k < 64 * EP / 4; k += 256) dstT[k] = srcT[k];
            if (t < 64) sg[t] = g_gv[b][p][i0 + t];
        }
        __syncthreads();

        float Treg[4][EE];
        #pragma unroll
        for (int ii = 0; ii < 4; ii++) {
            int r = ii * 16 + ty;
            const float4 w0 = *(const float4*)&sT[r][0];
            const float4 w1 = *(const float4*)&sT[r][4];
            const float2 w2 = *(const float2*)&sT[r][8];
            Treg[ii][0] = w0.x; Treg[ii][1] = w0.y; Treg[ii][2] = w0.z; Treg[ii][3] = w0.w;
            Treg[ii][4] = w1.x; Treg[ii][5] = w1.y; Treg[ii][6] = w1.z; Treg[ii][7] = w1.w;
            Treg[ii][8] = w2.x; Treg[ii][9] = w2.y;
        }

        float racc[4] = {0.f, 0.f, 0.f, 0.f};

        for (int j0 = 0; j0 < NP; j0 += 64) {
            {
                const float4* srcP = (const float4*)&g_Pp[b][d][j0][0];
                float4* dstP = (float4*)&sP[0][0];
                for (int k = t; k < 64 * EP / 4; k += 256) dstP[k] = srcP[k];
                if (t < 64) sh[t] = g_hv[b][p][j0 + t];
            }
            __syncthreads();

            #pragma unroll
            for (int jj = 0; jj < 4; jj++) {
                int r = jj * 16 + tx;
                const float4 q0 = *(const float4*)&sP[r][0];
                const float4 q1 = *(const float4*)&sP[r][4];
                const float2 q2 = *(const float2*)&sP[r][8];
                float Pv[EE];
                Pv[0] = q0.x; Pv[1] = q0.y; Pv[2] = q0.z; Pv[3] = q0.w;
                Pv[4] = q1.x; Pv[5] = q1.y; Pv[6] = q1.z; Pv[7] = q1.w;
                Pv[8] = q2.x; Pv[9] = q2.y;
                float hj = sh[r];
                float m0 = 0.f, m1 = 0.f, m2 = 0.f, m3 = 0.f;
                #pragma unroll
                for (int e = 0; e < EE; e++) {
                    m0 = fmaf(Treg[0][e], Pv[e], m0);
                    m1 = fmaf(Treg[1][e], Pv[e], m1);
                    m2 = fmaf(Treg[2][e], Pv[e], m2);
                    m3 = fmaf(Treg[3][e], Pv[e], m3);
                }
                racc[0] = fmaf(ex2f(m0), hj, racc[0]);
                racc[1] = fmaf(ex2f(m1), hj, racc[1]);
                racc[2] = fmaf(ex2f(m2), hj, racc[2]);
                racc[3] = fmaf(ex2f(m3), hj, racc[3]);
            }
            __syncthreads();
        }

        #pragma unroll
        for (int ii = 0; ii < 4; ii++) acc = fmaf(sg[ii * 16 + ty], racc[ii], acc);
        __syncthreads();
    }

    float tot = blockReduceSum(acc, sred);
    if (t == 0) {
        g_EDD[b][a][d] = tot;
        g_EDD[b][d][a] = tot;
    }
}

// ---------------- kernel 4b: diagonal pairs (a==d), split over 4 i-chunks --
// grid = BB*DD*NCHUNK = 512 blocks -> ~3 blocks/SM, proper latency hiding.
__global__ void __launch_bounds__(256, 3) k_main_diag(const float* __restrict__ invK) {
    int bp = blockIdx.x;
    int c = bp & (NCHUNK - 1);
    int ba = bp >> 2;
    int b = ba / DD, a = ba % DD;
    int p = pfull(a, a);
    int t = threadIdx.x, tx = t & 15, ty = t >> 4;

    __shared__ __align__(16) float sT[32][EP];
    __shared__ __align__(16) float sP[64][EP];
    __shared__ float sg[32], sh[64], sg2[32], sh2[64];
    __shared__ float sred[32];

    const float* Krow = invK + (size_t)a * NP * NP;

    float acc = 0.f, tacc = 0.f;

    const int ibeg = c * (NP / NCHUNK);
    const int iend = ibeg + (NP / NCHUNK);

    for (int i0 = ibeg; i0 < iend; i0 += 32) {
        {
            const float4* srcT = (const float4*)&g_Tlp[b][p][i0][0];
            float4* dstT = (float4*)&sT[0][0];
            for (int k = t; k < 32 * EP / 4; k += 256) dstT[k] = srcT[k];
            if (t < 32) {
                sg[t] = g_gv[b][p][i0 + t];
                sg2[t] = g_g2[b][p][i0 + t];
            }
        }
        __syncthreads();

        float Treg[2][EE];
        #pragma unroll
        for (int ii = 0; ii < 2; ii++) {
            int r = ii * 16 + ty;   // rows ty and 16+ty
            const float4 w0 = *(const float4*)&sT[r][0];
            const float4 w1 = *(const float4*)&sT[r][4];
            const float2 w2 = *(const float2*)&sT[r][8];
            Treg[ii][0] = w0.x; Treg[ii][1] = w0.y; Treg[ii][2] = w0.z; Treg[ii][3] = w0.w;
            Treg[ii][4] = w1.x; Treg[ii][5] = w1.y; Treg[ii][6] = w1.z; Treg[ii][7] = w1.w;
            Treg[ii][8] = w2.x; Treg[ii][9] = w2.y;
        }

        float racc[2] = {0.f, 0.f};
        float t2acc[2] = {0.f, 0.f};

        for (int j0 = 0; j0 < NP; j0 += 64) {
            {
                const float4* srcP = (const float4*)&g_Pp[b][a][j0][0];
                float4* dstP = (float4*)&sP[0][0];
                for (int k = t; k < 64 * EP / 4; k += 256) dstP[k] = srcP[k];
                if (t < 64) {
                    sh[t] = g_hv[b][p][j0 + t];
                    sh2[t] = g_h2[b][p][j0 + t];
                }
            }
            __syncthreads();

            #pragma unroll
            for (int jj = 0; jj < 4; jj++) {
                int r = jj * 16 + tx;
                const float4 q0 = *(const float4*)&sP[r][0];
                const float4 q1 = *(const float4*)&sP[r][4];
                const float2 q2 = *(const float2*)&sP[r][8];
                float Pv[EE];
                Pv[0] = q0.x; Pv[1] = q0.y; Pv[2] = q0.z; Pv[3] = q0.w;
                Pv[4] = q1.x; Pv[5] = q1.y; Pv[6] = q1.z; Pv[7] = q1.w;
                Pv[8] = q2.x; Pv[9] = q2.y;
                float hj = sh[r], h2j = sh2[r];
                float k0 = Krow[(size_t)(i0 + ty) * NP + j0 + r];
                float k1 = Krow[(size_t)(i0 + 16 + ty) * NP + j0 + r];
                float m0 = 0.f, m1 = 0.f;
                #pragma unroll
                for (int e = 0; e < EE; e++) {
                    m0 = fmaf(Treg[0][e], Pv[e], m0);
                    m1 = fmaf(Treg[1][e], Pv[e], m1);
                }
                float e0 = ex2f(m0), e1 = ex2f(m1);
                racc[0] = fmaf(e0, hj, racc[0]);
                racc[1] = fmaf(e1, hj, racc[1]);
                t2acc[0] = fmaf(e0 * h2j, k0, t2acc[0]);
                t2acc[1] = fmaf(e1 * h2j, k1, t2acc[1]);
            }
            __syncthreads();
        }

        #pragma unroll
        for (int ii = 0; ii < 2; ii++) {
            int r = ii * 16 + ty;
            acc = fmaf(sg[r], racc[ii], acc);
            tacc = fmaf(sg2[r], t2acc[ii], tacc);
        }
        __syncthreads();
    }

    float tot = blockReduceSum(acc, sred);
    float tt = blockReduceSum(tacc, sred);
    if (t == 0) {
        g_EDDd[c][b][a] = tot;
        g_trp[c][b][a] = tt;
    }
}

// ---------------- kernel 5: final assembly ---------------------------------
__global__ void __launch_bounds__(64)
k_final(const float* __restrict__ obs_mean, const float* __restrict__ obs_var,
        const float* __restrict__ alpha_sq, const float* __restrict__ sigma_sq_eps,
        float* __restrict__ out) {
    int b = blockIdx.x, t = threadIdx.x;
    if (t < DD) {
        out[b * DD + t] = obs_mean[b * DD + t] + g_mu_delta[b][t];
    }
    if (t < DD * DD) {
        int i = t / DD, j = t % DD;
        float edd;
        if (i == j) {
            edd = 0.f;
            #pragma unroll
            for (int c = 0; c < NCHUNK; c++) edd += g_EDDd[c][b][i];
        } else {
            edd = g_EDD[b][i][j];
        }
        float sd = edd - g_mu_delta[b][i] * g_mu_delta[b][j];
        if (i == j) {
            float tr = 0.f;
            #pragma unroll
            for (int c = 0; c < NCHUNK; c++) tr += g_trp[c][b][i];
            sd += alpha_sq[i] - tr + sigma_sq_eps[i];
        }
        float v = obs_var[b * DD * DD + i * DD + j] + sd + g_V[b][j][i] + g_V[b][i][j];
        out[BB * DD + b * DD * DD + i * DD + j] = v;
    }
}

extern "C" void kernel_launch(void* const* d_in, const int* in_sizes, int n_in,
                              void* d_out, int out_size) {
    const float* obs_mean     = (const float*)d_in[0];
    const float* obs_var      = (const float*)d_in[1];
    const float* action_mean  = (const float*)d_in[2];
    const float* action_var   = (const float*)d_in[3];
    const float* cross_cov    = (const float*)d_in[4];
    const float* X_train      = (const float*)d_in[5];
    const float* ell          = (const float*)d_in[6];
    const float* alpha_sq     = (const float*)d_in[7];
    const float* sigma_sq_eps = (const float*)d_in[8];
    const float* beta         = (const float*)d_in[9];
    const float* inv_K        = (const float*)d_in[10];
    float* out = (float*)d_out;

    k_prep<<<BB, NP>>>(obs_mean, obs_var, action_mean, action_var, cross_cov,
                       X_train, ell, alpha_sq);
    k_perdim<<<BB * DD, NP>>>(ell, alpha_sq, beta);
    k_pairprep<<<BB * NPAIR, NP>>>(ell, beta);
    k_main_off<<<BB * NOFF, 256>>>();
    k_main_diag<<<BB * DD * NCHUNK, 256>>>(inv_K);
    k_final<<<BB, 64>>>(obs_mean, obs_var, alpha_sq, sigma_sq_eps, out);
}

// round 14
// speedup vs baseline: 2.8642x; 1.1038x over previous
#include <cuda_runtime.h>
#include <math.h>

#define BB 16
#define DD 8
#define FF 2
#define EE 10
#define EP 12          // padded row (float4-aligned, 48B = 3x16B, odd multiple of 16)
#define NP 512
#define NPAIR 36
#define NOFF 28
#define NCHUNK 4       // i-chunks for the diagonal kernel
#define LOG2E 1.4426950408889634f

// ---------------- scratch (device globals; no allocation allowed) ----------
__device__ float g_Pp[BB][DD][NP][EP];       // padded P (written by diag blocks of k_all)
__device__ float g_mu_delta[BB][DD];
__device__ float g_V[BB][DD][EE];
__device__ float g_Tlp[BB][NPAIR][NP][EP];   // (Pa @ S) * log2(e), padded
__device__ float g_gv[BB][NPAIR][NP];
__device__ float g_hv[BB][NPAIR][NP];
__device__ float g_g2[BB][NPAIR][NP];
__device__ float g_h2[BB][NPAIR][NP];
__device__ float g_EDD[BB][DD][DD];
__device__ float g_EDDd[NCHUNK][BB][DD];     // diag partials per i-chunk
__device__ float g_trp[NCHUNK][BB][DD];      // trace partials per i-chunk

__device__ __forceinline__ float ex2f(float x) {
    float y;
    asm("ex2.approx.ftz.f32 %0, %1;" : "=f"(y) : "f"(x));
    return y;
}

__device__ __forceinline__ void pair_of(int p, int &a, int &d) {
    int aa = 0;
    while (p >= DD - aa) { p -= DD - aa; aa++; }
    a = aa; d = aa + p;
}
__device__ __forceinline__ void pair_off(int p, int &a, int &d) {
    int aa = 0;
    while (p >= DD - 1 - aa) { p -= DD - 1 - aa; aa++; }
    a = aa; d = aa + 1 + p;
}
// index of (a,d), a<=d, in pair_of enumeration
__device__ __forceinline__ int pfull(int a, int d) {
    return a * (2 * DD - a + 1) / 2 + (d - a);
}

__device__ float blockReduceSum(float v, float* sred) {
    const unsigned full = 0xffffffffu;
    #pragma unroll
    for (int o = 16; o > 0; o >>= 1) v += __shfl_down_sync(full, v, o);
    int t = threadIdx.x, warp = t >> 5, lane = t & 31;
    int nw = blockDim.x >> 5;
    if (lane == 0) sred[warp] = v;
    __syncthreads();
    float r = (t < nw) ? sred[t] : 0.f;
    if (warp == 0) {
        #pragma unroll
        for (int o = 16; o > 0; o >>= 1) r += __shfl_down_sync(full, r, o);
        if (lane == 0) sred[0] = r;
    }
    __syncthreads();
    float out = sred[0];
    __syncthreads();
    return out;
}

// Gauss-Jordan in shared memory; warp 0 cooperates, lanes = columns.
__device__ void gj_solve10(float (*M)[EE + 1], float (*X)[EE + 1], float* ldout) {
    int t = threadIdx.x;
    if (t < 32) {
        int lane = t;
        float ld = 0.f;
        for (int k = 0; k < EE; k++) {
            float piv = M[k][k];
            ld += logf(fabsf(piv));
            float inv = 1.f / piv;
            __syncwarp();
            if (lane < EE) { M[k][lane] *= inv; X[k][lane] *= inv; }
            __syncwarp();
            for (int r = 0; r < EE; r++) {
                if (r == k) continue;
                float fac = M[r][k];
                __syncwarp();
                if (lane < EE) {
                    M[r][lane] -= fac * M[k][lane];
                    X[r][lane] -= fac * X[k][lane];
                }
                __syncwarp();
            }
        }
        if (lane == 0) *ldout = ld;
    }
    __syncthreads();
}

// ---------------- kernel 1 (fused prep): per (b,pair) ----------------------
// Rebuilds Sigma/mu locally, computes nu/P/logk in registers, solves R->S,
// emits T/g/h. Diagonal-pair blocks additionally do the per-dim work
// (A-solve, q, mu_delta, V) and publish g_Pp for the main kernels.
__global__ void __launch_bounds__(NP)
k_all(const float* __restrict__ obs_mean, const float* __restrict__ obs_var,
      const float* __restrict__ action_mean, const float* __restrict__ action_var,
      const float* __restrict__ cross_cov, const float* __restrict__ X_train,
      const float* __restrict__ ell, const float* __restrict__ alpha_sq,
      const float* __restrict__ beta) {
    int bp = blockIdx.x;
    int b = bp / NPAIR, p = bp % NPAIR;
    int a, d;
    pair_of(p, a, d);
    const bool diag = (a == d);
    int t = threadIdx.x;

    __shared__ float sSig[EE][EE + 1];
    __shared__ float sM[EE][EE + 1], sX[EE][EE + 1];
    __shared__ float smu[EE], siA[EE], siD[EE];
    __shared__ float sld, sldA;
    __shared__ float slal2[2];
    __shared__ float sred[32];

    if (t < DD) smu[t] = obs_mean[b * DD + t];
    else if (t < EE) smu[t] = action_mean[b * FF + (t - DD)];
    if (t >= 32 && t < 32 + EE) {
        int e = t - 32; float l = ell[a * EE + e]; siA[e] = 1.f / (l * l);
    }
    if (t >= 64 && t < 64 + EE) {
        int e = t - 64; float l = ell[d * EE + e]; siD[e] = 1.f / (l * l);
    }
    if (t == 96) slal2[0] = logf(alpha_sq[a]);
    if (t == 97) slal2[1] = logf(alpha_sq[d]);
    if (t >= 128 && t < 128 + EE * EE) {
        int q = t - 128, e = q / EE, f = q % EE;
        float v;
        if (e < DD && f < DD)      v = obs_var[b * DD * DD + e * DD + f];
        else if (e < DD)           v = cross_cov[b * DD * FF + e * FF + (f - DD)];
        else if (f < DD)           v = cross_cov[b * DD * FF + f * FF + (e - DD)];
        else                       v = action_var[b * FF * FF + (e - DD) * FF + (f - DD)];
        sSig[e][f] = v;
    }
    __syncthreads();

    if (t < EE * EE) {
        int e = t / EE, f = t % EE;
        sM[e][f] = sSig[e][f] * (siA[f] + siD[f]) + ((e == f) ? 1.f : 0.f);
        sX[e][f] = sSig[e][f];
    }
    __syncthreads();
    gj_solve10(sM, sX, &sld);  // sX = S = R^{-1} Sigma, sld = logdetR

    int n = t;
    float nu[EE], Pa[EE], Pd[EE];
    float ka = slal2[0], kd = slal2[1];
    #pragma unroll
    for (int e = 0; e < EE; e++) {
        nu[e] = X_train[n * EE + e] - smu[e];
        Pa[e] = nu[e] * siA[e];
        Pd[e] = nu[e] * siD[e];
        ka -= 0.5f * nu[e] * Pa[e];
        kd -= 0.5f * nu[e] * Pd[e];
    }

    // a-side: T = Pa @ S, g
    {
        float Tv[EE];
        #pragma unroll
        for (int e = 0; e < EE; e++) {
            float acc = 0.f;
            #pragma unroll
            for (int f = 0; f < EE; f++) acc = fmaf(Pa[f], sX[f][e], acc);
            Tv[e] = acc;
        }
        float da = 0.f;
        #pragma unroll
        for (int e = 0; e < EE; e++) da = fmaf(Tv[e], Pa[e], da);
        #pragma unroll
        for (int e = 0; e < EE; e++) g_Tlp[b][p][n][e] = Tv[e] * LOG2E;
        g_Tlp[b][p][n][10] = 0.f;
        g_Tlp[b][p][n][11] = 0.f;
        float g2 = __expf(ka + 0.5f * da - 0.25f * sld);
        g_g2[b][p][n] = g2;
        g_gv[b][p][n] = beta[a * NP + n] * g2;
    }
    // d-side: h
    {
        float Tv[EE];
        #pragma unroll
        for (int e = 0; e < EE; e++) {
            float acc = 0.f;
            #pragma unroll
            for (int f = 0; f < EE; f++) acc = fmaf(Pd[f], sX[f][e], acc);
            Tv[e] = acc;
        }
        float db = 0.f;
        #pragma unroll
        for (int e = 0; e < EE; e++) db = fmaf(Tv[e], Pd[e], db);
        float h2 = __expf(kd + 0.5f * db - 0.25f * sld);
        g_h2[b][p][n] = h2;
        g_hv[b][p][n] = beta[d * NP + n] * h2;
    }

    if (diag) {
        // publish P for the main kernels
        #pragma unroll
        for (int e = 0; e < EE; e++) g_Pp[b][d][n][e] = Pd[e];
        g_Pp[b][d][n][10] = 0.f;
        g_Pp[b][d][n][11] = 0.f;

        // per-dim: A = Sigma + diag(ell_d^2), Ainv, q, mu_delta, w, V
        __syncthreads();
        if (t < EE * EE) {
            int e = t / EE, f = t % EE;
            sM[e][f] = sSig[e][f] + ((e == f) ? (1.f / siD[e]) : 0.f);
            sX[e][f] = (e == f) ? 1.f : 0.f;
        }
        __syncthreads();
        gj_solve10(sM, sX, &sldA);  // sX = Ainv, sldA = logdetA

        float ldl = 0.f;
        #pragma unroll
        for (int e = 0; e < EE; e++) ldl -= logf(siD[e]);

        float quad = 0.f;
        #pragma unroll
        for (int e = 0; e < EE; e++) {
            float acc = 0.f;
            #pragma unroll
            for (int f = 0; f < EE; f++) acc = fmaf(sX[e][f], nu[f], acc);
            quad = fmaf(nu[e], acc, quad);
        }
        float q = alpha_sq[d] * __expf(0.5f * (ldl - sldA) - 0.5f * quad);
        float bq = beta[d * NP + n] * q;

        float md = blockReduceSum(bq, sred);
        float wreg[EE];
        for (int e = 0; e < EE; e++) wreg[e] = blockReduceSum(bq * nu[e], sred);

        if (t == 0) {
            g_mu_delta[b][d] = md;
            float u[EE];
            for (int e = 0; e < EE; e++) {
                float acc = 0.f;
                for (int f = 0; f < EE; f++) acc = fmaf(sX[e][f], wreg[f], acc);
                u[e] = acc;
            }
            for (int e = 0; e < EE; e++) {
                float acc = 0.f;
                for (int f = 0; f < EE; f++) acc = fmaf(sSig[e][f], u[f], acc);
                g_V[b][d][e] = acc;
            }
        }
    }
}

// ---------------- kernel 2a: off-diagonal pairs (a<d) ----------------------
// Cyclic micro-tile mapping (conflict-free LDS). At the FMA roofline; unchanged.
__global__ void __launch_bounds__(256, 3) k_main_off() {
    int bp = blockIdx.x;
    int b = bp / NOFF, p28 = bp % NOFF;
    int a, d;
    pair_off(p28, a, d);
    int p = pfull(a, d);
    int t = threadIdx.x, tx = t & 15, ty = t >> 4;

    __shared__ __align__(16) float sT[64][EP];
    __shared__ __align__(16) float sP[64][EP];
    __shared__ float sg[64], sh[64];
    __shared__ float sred[32];

    float acc = 0.f;

    for (int i0 = 0; i0 < NP; i0 += 64) {
        {
            const float4* srcT = (const float4*)&g_Tlp[b][p][i0][0];
            float4* dstT = (float4*)&sT[0][0];
            for (int k = t; k < 64 * EP / 4; k += 256) dstT[k] = srcT[k];
            if (t < 64) sg[t] = g_gv[b][p][i0 + t];
        }
        __syncthreads();

        float Treg[4][EE];
        #pragma unroll
        for (int ii = 0; ii < 4; ii++) {
            int r = ii * 16 + ty;
            const float4 w0 = *(const float4*)&sT[r][0];
            const float4 w1 = *(const float4*)&sT[r][4];
            const float2 w2 = *(const float2*)&sT[r][8];
            Treg[ii][0] = w0.x; Treg[ii][1] = w0.y; Treg[ii][2] = w0.z; Treg[ii][3] = w0.w;
            Treg[ii][4] = w1.x; Treg[ii][5] = w1.y; Treg[ii][6] = w1.z; Treg[ii][7] = w1.w;
            Treg[ii][8] = w2.x; Treg[ii][9] = w2.y;
        }

        float racc[4] = {0.f, 0.f, 0.f, 0.f};

        for (int j0 = 0; j0 < NP; j0 += 64) {
            {
                const float4* srcP = (const float4*)&g_Pp[b][d][j0][0];
                float4* dstP = (float4*)&sP[0][0];
                for (int k = t; k < 64 * EP / 4; k += 256) dstP[k] = srcP[k];
                if (t < 64) sh[t] = g_hv[b][p][j0 + t];
            }
            __syncthreads();

            #pragma unroll
            for (int jj = 0; jj < 4; jj++) {
                int r = jj * 16 + tx;
                const float4 q0 = *(const float4*)&sP[r][0];
                const float4 q1 = *(const float4*)&sP[r][4];
                const float2 q2 = *(const float2*)&sP[r][8];
                float Pv[EE];
                Pv[0] = q0.x; Pv[1] = q0.y; Pv[2] = q0.z; Pv[3] = q0.w;
                Pv[4] = q1.x; Pv[5] = q1.y; Pv[6] = q1.z; Pv[7] = q1.w;
                Pv[8] = q2.x; Pv[9] = q2.y;
                float hj = sh[r];
                float m0 = 0.f, m1 = 0.f, m2 = 0.f, m3 = 0.f;
                #pragma unroll
                for (int e = 0; e < EE; e++) {
                    m0 = fmaf(Treg[0][e], Pv[e], m0);
                    m1 = fmaf(Treg[1][e], Pv[e], m1);
                    m2 = fmaf(Treg[2][e], Pv[e], m2);
                    m3 = fmaf(Treg[3][e], Pv[e], m3);
                }
                racc[0] = fmaf(ex2f(m0), hj, racc[0]);
                racc[1] = fmaf(ex2f(m1), hj, racc[1]);
                racc[2] = fmaf(ex2f(m2), hj, racc[2]);
                racc[3] = fmaf(ex2f(m3), hj, racc[3]);
            }
            __syncthreads();
        }

        #pragma unroll
        for (int ii = 0; ii < 4; ii++) acc = fmaf(sg[ii * 16 + ty], racc[ii], acc);
        __syncthreads();
    }

    float tot = blockReduceSum(acc, sred);
    if (t == 0) {
        g_EDD[b][a][d] = tot;
        g_EDD[b][d][a] = tot;
    }
}

// ---------------- kernel 2b: diagonal pairs (a==d), split over 4 i-chunks --
__global__ void __launch_bounds__(256, 3) k_main_diag(const float* __restrict__ invK) {
    int bp = blockIdx.x;
    int c = bp & (NCHUNK - 1);
    int ba = bp >> 2;
    int b = ba / DD, a = ba % DD;
    int p = pfull(a, a);
    int t = threadIdx.x, tx = t & 15, ty = t >> 4;

    __shared__ __align__(16) float sT[32][EP];
    __shared__ __align__(16) float sP[64][EP];
    __shared__ float sg[32], sh[64], sg2[32], sh2[64];
    __shared__ float sred[32];

    const float* Krow = invK + (size_t)a * NP * NP;

    float acc = 0.f, tacc = 0.f;

    const int ibeg = c * (NP / NCHUNK);
    const int iend = ibeg + (NP / NCHUNK);

    for (int i0 = ibeg; i0 < iend; i0 += 32) {
        {
            const float4* srcT = (const float4*)&g_Tlp[b][p][i0][0];
            float4* dstT = (float4*)&sT[0][0];
            for (int k = t; k < 32 * EP / 4; k += 256) dstT[k] = srcT[k];
            if (t < 32) {
                sg[t] = g_gv[b][p][i0 + t];
                sg2[t] = g_g2[b][p][i0 + t];
            }
        }
        __syncthreads();

        float Treg[2][EE];
        #pragma unroll
        for (int ii = 0; ii < 2; ii++) {
            int r = ii * 16 + ty;   // rows ty and 16+ty
            const float4 w0 = *(const float4*)&sT[r][0];
            const float4 w1 = *(const float4*)&sT[r][4];
            const float2 w2 = *(const float2*)&sT[r][8];
            Treg[ii][0] = w0.x; Treg[ii][1] = w0.y; Treg[ii][2] = w0.z; Treg[ii][3] = w0.w;
            Treg[ii][4] = w1.x; Treg[ii][5] = w1.y; Treg[ii][6] = w1.z; Treg[ii][7] = w1.w;
            Treg[ii][8] = w2.x; Treg[ii][9] = w2.y;
        }

        float racc[2] = {0.f, 0.f};
        float t2acc[2] = {0.f, 0.f};

        for (int j0 = 0; j0 < NP; j0 += 64) {
            {
                const float4* srcP = (const float4*)&g_Pp[b][a][j0][0];
                float4* dstP = (float4*)&sP[0][0];
                for (int k = t; k < 64 * EP / 4; k += 256) dstP[k] = srcP[k];
                if (t < 64) {
                    sh[t] = g_hv[b][p][j0 + t];
                    sh2[t] = g_h2[b][p][j0 + t];
                }
            }
            __syncthreads();

            #pragma unroll
            for (int jj = 0; jj < 4; jj++) {
                int r = jj * 16 + tx;
                const float4 q0 = *(const float4*)&sP[r][0];
                const float4 q1 = *(const float4*)&sP[r][4];
                const float2 q2 = *(const float2*)&sP[r][8];
                float Pv[EE];
                Pv[0] = q0.x; Pv[1] = q0.y; Pv[2] = q0.z; Pv[3] = q0.w;
                Pv[4] = q1.x; Pv[5] = q1.y; Pv[6] = q1.z; Pv[7] = q1.w;
                Pv[8] = q2.x; Pv[9] = q2.y;
                float hj = sh[r], h2j = sh2[r];
                float k0 = Krow[(size_t)(i0 + ty) * NP + j0 + r];
                float k1 = Krow[(size_t)(i0 + 16 + ty) * NP + j0 + r];
                float m0 = 0.f, m1 = 0.f;
                #pragma unroll
                for (int e = 0; e < EE; e++) {
                    m0 = fmaf(Treg[0][e], Pv[e], m0);
                    m1 = fmaf(Treg[1][e], Pv[e], m1);
                }
                float e0 = ex2f(m0), e1 = ex2f(m1);
                racc[0] = fmaf(e0, hj, racc[0]);
                racc[1] = fmaf(e1, hj, racc[1]);
                t2acc[0] = fmaf(e0 * h2j, k0, t2acc[0]);
                t2acc[1] = fmaf(e1 * h2j, k1, t2acc[1]);
            }
            __syncthreads();
        }

        #pragma unroll
        for (int ii = 0; ii < 2; ii++) {
            int r = ii * 16 + ty;
            acc = fmaf(sg[r], racc[ii], acc);
            tacc = fmaf(sg2[r], t2acc[ii], tacc);
        }
        __syncthreads();
    }

    float tot = blockReduceSum(acc, sred);
    float tt = blockReduceSum(tacc, sred);
    if (t == 0) {
        g_EDDd[c][b][a] = tot;
        g_trp[c][b][a] = tt;
    }
}

// ---------------- kernel 3: final assembly ---------------------------------
__global__ void __launch_bounds__(64)
k_final(const float* __restrict__ obs_mean, const float* __restrict__ obs_var,
        const float* __restrict__ alpha_sq, const float* __restrict__ sigma_sq_eps,
        float* __restrict__ out) {
    int b = blockIdx.x, t = threadIdx.x;
    if (t < DD) {
        out[b * DD + t] = obs_mean[b * DD + t] + g_mu_delta[b][t];
    }
    if (t < DD * DD) {
        int i = t / DD, j = t % DD;
        float edd;
        if (i == j) {
            edd = 0.f;
            #pragma unroll
            for (int c = 0; c < NCHUNK; c++) edd += g_EDDd[c][b][i];
        } else {
            edd = g_EDD[b][i][j];
        }
        float sd = edd - g_mu_delta[b][i] * g_mu_delta[b][j];
        if (i == j) {
            float tr = 0.f;
            #pragma unroll
            for (int c = 0; c < NCHUNK; c++) tr += g_trp[c][b][i];
            sd += alpha_sq[i] - tr + sigma_sq_eps[i];
        }
        float v = obs_var[b * DD * DD + i * DD + j] + sd + g_V[b][j][i] + g_V[b][i][j];
        out[BB * DD + b * DD * DD + i * DD + j] = v;
    }
}

extern "C" void kernel_launch(void* const* d_in, const int* in_sizes, int n_in,
                              void* d_out, int out_size) {
    const float* obs_mean     = (const float*)d_in[0];
    const float* obs_var      = (const float*)d_in[1];
    const float* action_mean  = (const float*)d_in[2];
    const float* action_var   = (const float*)d_in[3];
    const float* cross_cov    = (const float*)d_in[4];
    const float* X_train      = (const float*)d_in[5];
    const float* ell          = (const float*)d_in[6];
    const float* alpha_sq     = (const float*)d_in[7];
    const float* sigma_sq_eps = (const float*)d_in[8];
    const float* beta         = (const float*)d_in[9];
    const float* inv_K        = (const float*)d_in[10];
    float* out = (float*)d_out;

    k_all<<<BB * NPAIR, NP>>>(obs_mean, obs_var, action_mean, action_var,
                              cross_cov, X_train, ell, alpha_sq, beta);
    k_main_off<<<BB * NOFF, 256>>>();
    k_main_diag<<<BB * DD * NCHUNK, 256>>>(inv_K);
    k_final<<<BB, 64>>>(obs_mean, obs_var, alpha_sq, sigma_sq_eps, out);
}

// round 15
// speedup vs baseline: 3.3658x; 1.1751x over previous
#include <cuda_runtime.h>
#include <math.h>

#define BB 16
#define DD 8
#define FF 2
#define EE 10
#define EP 12          // padded row (float4-aligned, 48B = 3x16B, odd multiple of 16)
#define NP 512
#define NPAIR 36
#define NOFF 28
#define NCHUNK 4       // i-chunks for the diagonal kernel
#define LOG2E 1.4426950408889634f

// ---------------- scratch (device globals; no allocation allowed) ----------
__device__ float g_S[BB][NPAIR][EE][EE];     // S = R^{-1} Sigma  (same layout as old sX)
__device__ float g_ldR[BB][NPAIR];
__device__ float g_Ainv[BB][DD][EE][EE];
__device__ float g_ldA[BB][DD];
__device__ float g_Pp[BB][DD][NP][EP];       // padded P
__device__ float g_mu_delta[BB][DD];
__device__ float g_V[BB][DD][EE];
__device__ float g_Tlp[BB][NPAIR][NP][EP];   // (Pa @ S) * log2(e), padded
__device__ float g_gv[BB][NPAIR][NP];
__device__ float g_hv[BB][NPAIR][NP];
__device__ float g_g2[BB][NPAIR][NP];
__device__ float g_h2[BB][NPAIR][NP];
__device__ float g_EDD[BB][DD][DD];
__device__ float g_EDDd[NCHUNK][BB][DD];     // diag partials per i-chunk
__device__ float g_trp[NCHUNK][BB][DD];      // trace partials per i-chunk

__device__ __forceinline__ float ex2f(float x) {
    float y;
    asm("ex2.approx.ftz.f32 %0, %1;" : "=f"(y) : "f"(x));
    return y;
}

__device__ __forceinline__ void pair_of(int p, int &a, int &d) {
    int aa = 0;
    while (p >= DD - aa) { p -= DD - aa; aa++; }
    a = aa; d = aa + p;
}
__device__ __forceinline__ void pair_off(int p, int &a, int &d) {
    int aa = 0;
    while (p >= DD - 1 - aa) { p -= DD - 1 - aa; aa++; }
    a = aa; d = aa + 1 + p;
}
__device__ __forceinline__ int pfull(int a, int d) {
    return a * (2 * DD - a + 1) / 2 + (d - a);
}

__device__ float blockReduceSum(float v, float* sred) {
    const unsigned full = 0xffffffffu;
    #pragma unroll
    for (int o = 16; o > 0; o >>= 1) v += __shfl_down_sync(full, v, o);
    int t = threadIdx.x, warp = t >> 5, lane = t & 31;
    int nw = blockDim.x >> 5;
    if (lane == 0) sred[warp] = v;
    __syncthreads();
    float r = (t < nw) ? sred[t] : 0.f;
    if (warp == 0) {
        #pragma unroll
        for (int o = 16; o > 0; o >>= 1) r += __shfl_down_sync(full, r, o);
        if (lane == 0) sred[0] = r;
    }
    __syncthreads();
    float out = sred[0];
    __syncthreads();
    return out;
}

// Build Sigma[e][f] for batch b from the inputs (each thread computes one element).
__device__ __forceinline__ float sigma_elem(
    int b, int e, int f,
    const float* __restrict__ obs_var, const float* __restrict__ action_var,
    const float* __restrict__ cross_cov) {
    if (e < DD && f < DD)      return obs_var[b * DD * DD + e * DD + f];
    else if (e < DD)           return cross_cov[b * DD * FF + e * FF + (f - DD)];
    else if (f < DD)           return cross_cov[b * DD * FF + f * FF + (e - DD)];
    else                       return action_var[b * FF * FF + (e - DD) * FF + (f - DD)];
}

// ---------------- kernel 0: all 10x10 solves, one warp per solve -----------
// bid < BB*NPAIR:  R-solve for (b,p):  [Sig*(siA+siD)+I | Sig] -> S, logdetR
// bid >= BB*NPAIR: A-solve for (b,d):  [Sig+diag(ell_d^2) | I] -> Ainv, logdetA
__global__ void __launch_bounds__(32)
k_solve(const float* __restrict__ obs_var, const float* __restrict__ action_var,
        const float* __restrict__ cross_cov, const float* __restrict__ ell) {
    int bid = blockIdx.x;
    int lane = threadIdx.x;
    const bool isR = (bid < BB * NPAIR);

    __shared__ float W[EE][2 * EE];   // [M | X]
    __shared__ float sfac[EE];
    __shared__ float spinv;

    int b, a, d;
    if (isR) {
        b = bid / NPAIR;
        int p = bid % NPAIR;
        pair_of(p, a, d);
    } else {
        int idx = bid - BB * NPAIR;
        b = idx / DD;
        a = d = idx % DD;
    }

    // fill augmented system
    for (int idx = lane; idx < EE * EE; idx += 32) {
        int e = idx / EE, f = idx % EE;
        float sig = sigma_elem(b, e, f, obs_var, action_var, cross_cov);
        if (isR) {
            float la = ell[a * EE + f], ld2 = ell[d * EE + f];
            float ils = 1.f / (la * la) + 1.f / (ld2 * ld2);
            W[e][f] = sig * ils + ((e == f) ? 1.f : 0.f);
            W[e][EE + f] = sig;
        } else {
            float l = ell[d * EE + e];
            W[e][f] = sig + ((e == f) ? (l * l) : 0.f);
            W[e][EE + f] = (e == f) ? 1.f : 0.f;
        }
    }
    __syncwarp();

    float ld = 0.f;
    for (int k = 0; k < EE; k++) {
        if (lane == 0) {
            float piv = W[k][k];
            ld += logf(fabsf(piv));
            spinv = 1.f / piv;
        }
        __syncwarp();
        if (lane < 2 * EE) W[k][lane] *= spinv;
        __syncwarp();
        if (lane < EE) sfac[lane] = (lane == k) ? 0.f : W[lane][k];
        __syncwarp();
        // update the other 9 rows x 20 cols = 180 elements
        for (int idx = lane; idx < (EE - 1) * 2 * EE; idx += 32) {
            int rr = idx / (2 * EE), c = idx % (2 * EE);
            int r = rr + (rr >= k ? 1 : 0);
            W[r][c] -= sfac[r] * W[k][c];
        }
        __syncwarp();
    }

    // write out X part and logdet
    if (isR) {
        int p = bid % NPAIR;
        for (int idx = lane; idx < EE * EE; idx += 32)
            g_S[b][p][idx / EE][idx % EE] = W[idx / EE][EE + idx % EE];
        if (lane == 0) g_ldR[b][p] = ld;
    } else {
        for (int idx = lane; idx < EE * EE; idx += 32)
            g_Ainv[b][d][idx / EE][idx % EE] = W[idx / EE][EE + idx % EE];
        if (lane == 0) g_ldA[b][d] = ld;
    }
}

// ---------------- kernel 1: emission per (b,pair), no GJ -------------------
__global__ void __launch_bounds__(NP)
k_emit(const float* __restrict__ obs_mean, const float* __restrict__ obs_var,
       const float* __restrict__ action_mean, const float* __restrict__ action_var,
       const float* __restrict__ cross_cov, const float* __restrict__ X_train,
       const float* __restrict__ ell, const float* __restrict__ alpha_sq,
       const float* __restrict__ beta) {
    int bp = blockIdx.x;
    int b = bp / NPAIR, p = bp % NPAIR;
    int a, d;
    pair_of(p, a, d);
    const bool diag = (a == d);
    int t = threadIdx.x;

    __shared__ float sX[EE][EE + 1];     // S (R-solve result)
    __shared__ float sSig[EE][EE + 1];
    __shared__ float smu[EE], siA[EE], siD[EE];
    __shared__ float slal2[2];
    __shared__ float sred[32];

    if (t < DD) smu[t] = obs_mean[b * DD + t];
    else if (t < EE) smu[t] = action_mean[b * FF + (t - DD)];
    if (t >= 32 && t < 32 + EE) {
        int e = t - 32; float l = ell[a * EE + e]; siA[e] = 1.f / (l * l);
    }
    if (t >= 64 && t < 64 + EE) {
        int e = t - 64; float l = ell[d * EE + e]; siD[e] = 1.f / (l * l);
    }
    if (t == 96) slal2[0] = logf(alpha_sq[a]);
    if (t == 97) slal2[1] = logf(alpha_sq[d]);
    if (t >= 128 && t < 128 + EE * EE) {
        int q = t - 128, e = q / EE, f = q % EE;
        sX[e][f] = g_S[b][p][e][f];
    }
    if (t >= 256 && t < 256 + EE * EE) {
        int q = t - 256, e = q / EE, f = q % EE;
        sSig[e][f] = sigma_elem(b, e, f, obs_var, action_var, cross_cov);
    }
    __syncthreads();

    float sld = g_ldR[b][p];

    int n = t;
    float nu[EE], Pa[EE], Pd[EE];
    float ka = slal2[0], kd = slal2[1];
    #pragma unroll
    for (int e = 0; e < EE; e++) {
        nu[e] = X_train[n * EE + e] - smu[e];
        Pa[e] = nu[e] * siA[e];
        Pd[e] = nu[e] * siD[e];
        ka -= 0.5f * nu[e] * Pa[e];
        kd -= 0.5f * nu[e] * Pd[e];
    }

    // a-side: T = Pa @ S, g
    {
        float Tv[EE];
        #pragma unroll
        for (int e = 0; e < EE; e++) {
            float acc = 0.f;
            #pragma unroll
            for (int f = 0; f < EE; f++) acc = fmaf(Pa[f], sX[f][e], acc);
            Tv[e] = acc;
        }
        float da = 0.f;
        #pragma unroll
        for (int e = 0; e < EE; e++) da = fmaf(Tv[e], Pa[e], da);
        #pragma unroll
        for (int e = 0; e < EE; e++) g_Tlp[b][p][n][e] = Tv[e] * LOG2E;
        g_Tlp[b][p][n][10] = 0.f;
        g_Tlp[b][p][n][11] = 0.f;
        float g2 = __expf(ka + 0.5f * da - 0.25f * sld);
        g_g2[b][p][n] = g2;
        g_gv[b][p][n] = beta[a * NP + n] * g2;
    }
    // d-side: h
    {
        float Tv[EE];
        #pragma unroll
        for (int e = 0; e < EE; e++) {
            float acc = 0.f;
            #pragma unroll
            for (int f = 0; f < EE; f++) acc = fmaf(Pd[f], sX[f][e], acc);
            Tv[e] = acc;
        }
        float db = 0.f;
        #pragma unroll
        for (int e = 0; e < EE; e++) db = fmaf(Tv[e], Pd[e], db);
        float h2 = __expf(kd + 0.5f * db - 0.25f * sld);
        g_h2[b][p][n] = h2;
        g_hv[b][p][n] = beta[d * NP + n] * h2;
    }

    if (diag) {
        // publish P for the main kernels
        #pragma unroll
        for (int e = 0; e < EE; e++) g_Pp[b][d][n][e] = Pd[e];
        g_Pp[b][d][n][10] = 0.f;
        g_Pp[b][d][n][11] = 0.f;

        // load Ainv, then q, mu_delta, w, V
        __syncthreads();
        if (t >= 128 && t < 128 + EE * EE) {
            int q = t - 128, e = q / EE, f = q % EE;
            sX[e][f] = g_Ainv[b][d][e][f];
        }
        __syncthreads();
        float sldA = g_ldA[b][d];

        float ldl = 0.f;
        #pragma unroll
        for (int e = 0; e < EE; e++) ldl -= logf(siD[e]);

        float quad = 0.f;
        #pragma unroll
        for (int e = 0; e < EE; e++) {
            float acc = 0.f;
            #pragma unroll
            for (int f = 0; f < EE; f++) acc = fmaf(sX[e][f], nu[f], acc);
            quad = fmaf(nu[e], acc, quad);
        }
        float q = alpha_sq[d] * __expf(0.5f * (ldl - sldA) - 0.5f * quad);
        float bq = beta[d * NP + n] * q;

        float md = blockReduceSum(bq, sred);
        float wreg[EE];
        for (int e = 0; e < EE; e++) wreg[e] = blockReduceSum(bq * nu[e], sred);

        if (t == 0) {
            g_mu_delta[b][d] = md;
            float u[EE];
            for (int e = 0; e < EE; e++) {
                float acc = 0.f;
                for (int f = 0; f < EE; f++) acc = fmaf(sX[e][f], wreg[f], acc);
                u[e] = acc;
            }
            for (int e = 0; e < EE; e++) {
                float acc = 0.f;
                for (int f = 0; f < EE; f++) acc = fmaf(sSig[e][f], u[f], acc);
                g_V[b][d][e] = acc;
            }
        }
    }
}

// ---------------- kernel 2a: off-diagonal pairs (a<d) ----------------------
// Cyclic micro-tile mapping (conflict-free LDS). At the FMA roofline; unchanged.
__global__ void __launch_bounds__(256, 3) k_main_off() {
    int bp = blockIdx.x;
    int b = bp / NOFF, p28 = bp % NOFF;
    int a, d;
    pair_off(p28, a, d);
    int p = pfull(a, d);
    int t = threadIdx.x, tx = t & 15, ty = t >> 4;

    __shared__ __align__(16) float sT[64][EP];
    __shared__ __align__(16) float sP[64][EP];
    __shared__ float sg[64], sh[64];
    __shared__ float sred[32];

    float acc = 0.f;

    for (int i0 = 0; i0 < NP; i0 += 64) {
        {
            const float4* srcT = (const float4*)&g_Tlp[b][p][i0][0];
            float4* dstT = (float4*)&sT[0][0];
            for (int k = t; k < 64 * EP / 4; k += 256) dstT[k] = srcT[k];
            if (t < 64) sg[t] = g_gv[b][p][i0 + t];
        }
        __syncthreads();

        float Treg[4][EE];
        #pragma unroll
        for (int ii = 0; ii < 4; ii++) {
            int r = ii * 16 + ty;
            const float4 w0 = *(const float4*)&sT[r][0];
            const float4 w1 = *(const float4*)&sT[r][4];
            const float2 w2 = *(const float2*)&sT[r][8];
            Treg[ii][0] = w0.x; Treg[ii][1] = w0.y; Treg[ii][2] = w0.z; Treg[ii][3] = w0.w;
            Treg[ii][4] = w1.x; Treg[ii][5] = w1.y; Treg[ii][6] = w1.z; Treg[ii][7] = w1.w;
            Treg[ii][8] = w2.x; Treg[ii][9] = w2.y;
        }

        float racc[4] = {0.f, 0.f, 0.f, 0.f};

        for (int j0 = 0; j0 < NP; j0 += 64) {
            {
                const float4* srcP = (const float4*)&g_Pp[b][d][j0][0];
                float4* dstP = (float4*)&sP[0][0];
                for (int k = t; k < 64 * EP / 4; k += 256) dstP[k] = srcP[k];
                if (t < 64) sh[t] = g_hv[b][p][j0 + t];
            }
            __syncthreads();

            #pragma unroll
            for (int jj = 0; jj < 4; jj++) {
                int r = jj * 16 + tx;
                const float4 q0 = *(const float4*)&sP[r][0];
                const float4 q1 = *(const float4*)&sP[r][4];
                const float2 q2 = *(const float2*)&sP[r][8];
                float Pv[EE];
                Pv[0] = q0.x; Pv[1] = q0.y; Pv[2] = q0.z; Pv[3] = q0.w;
                Pv[4] = q1.x; Pv[5] = q1.y; Pv[6] = q1.z; Pv[7] = q1.w;
                Pv[8] = q2.x; Pv[9] = q2.y;
                float hj = sh[r];
                float m0 = 0.f, m1 = 0.f, m2 = 0.f, m3 = 0.f;
                #pragma unroll
                for (int e = 0; e < EE; e++) {
                    m0 = fmaf(Treg[0][e], Pv[e], m0);
                    m1 = fmaf(Treg[1][e], Pv[e], m1);
                    m2 = fmaf(Treg[2][e], Pv[e], m2);
                    m3 = fmaf(Treg[3][e], Pv[e], m3);
                }
                racc[0] = fmaf(ex2f(m0), hj, racc[0]);
                racc[1] = fmaf(ex2f(m1), hj, racc[1]);
                racc[2] = fmaf(ex2f(m2), hj, racc[2]);
                racc[3] = fmaf(ex2f(m3), hj, racc[3]);
            }
            __syncthreads();
        }

        #pragma unroll
        for (int ii = 0; ii < 4; ii++) acc = fmaf(sg[ii * 16 + ty], racc[ii], acc);
        __syncthreads();
    }

    float tot = blockReduceSum(acc, sred);
    if (t == 0) {
        g_EDD[b][a][d] = tot;
        g_EDD[b][d][a] = tot;
    }
}

// ---------------- kernel 2b: diagonal pairs (a==d), split over 4 i-chunks --
__global__ void __launch_bounds__(256, 3) k_main_diag(const float* __restrict__ invK) {
    int bp = blockIdx.x;
    int c = bp & (NCHUNK - 1);
    int ba = bp >> 2;
    int b = ba / DD, a = ba % DD;
    int p = pfull(a, a);
    int t = threadIdx.x, tx = t & 15, ty = t >> 4;

    __shared__ __align__(16) float sT[32][EP];
    __shared__ __align__(16) float sP[64][EP];
    __shared__ float sg[32], sh[64], sg2[32], sh2[64];
    __shared__ float sred[32];

    const float* Krow = invK + (size_t)a * NP * NP;

    float acc = 0.f, tacc = 0.f;

    const int ibeg = c * (NP / NCHUNK);
    const int iend = ibeg + (NP / NCHUNK);

    for (int i0 = ibeg; i0 < iend; i0 += 32) {
        {
            const float4* srcT = (const float4*)&g_Tlp[b][p][i0][0];
            float4* dstT = (float4*)&sT[0][0];
            for (int k = t; k < 32 * EP / 4; k += 256) dstT[k] = srcT[k];
            if (t < 32) {
                sg[t] = g_gv[b][p][i0 + t];
                sg2[t] = g_g2[b][p][i0 + t];
            }
        }
        __syncthreads();

        float Treg[2][EE];
        #pragma unroll
        for (int ii = 0; ii < 2; ii++) {
            int r = ii * 16 + ty;
            const float4 w0 = *(const float4*)&sT[r][0];
            const float4 w1 = *(const float4*)&sT[r][4];
            const float2 w2 = *(const float2*)&sT[r][8];
            Treg[ii][0] = w0.x; Treg[ii][1] = w0.y; Treg[ii][2] = w0.z; Treg[ii][3] = w0.w;
            Treg[ii][4] = w1.x; Treg[ii][5] = w1.y; Treg[ii][6] = w1.z; Treg[ii][7] = w1.w;
            Treg[ii][8] = w2.x; Treg[ii][9] = w2.y;
        }

        float racc[2] = {0.f, 0.f};
        float t2acc[2] = {0.f, 0.f};

        for (int j0 = 0; j0 < NP; j0 += 64) {
            {
                const float4* srcP = (const float4*)&g_Pp[b][a][j0][0];
                float4* dstP = (float4*)&sP[0][0];
                for (int k = t; k < 64 * EP / 4; k += 256) dstP[k] = srcP[k];
                if (t < 64) {
                    sh[t] = g_hv[b][p][j0 + t];
                    sh2[t] = g_h2[b][p][j0 + t];
                }
            }
            __syncthreads();

            #pragma unroll
            for (int jj = 0; jj < 4; jj++) {
                int r = jj * 16 + tx;
                const float4 q0 = *(const float4*)&sP[r][0];
                const float4 q1 = *(const float4*)&sP[r][4];
                const float2 q2 = *(const float2*)&sP[r][8];
                float Pv[EE];
                Pv[0] = q0.x; Pv[1] = q0.y; Pv[2] = q0.z; Pv[3] = q0.w;
                Pv[4] = q1.x; Pv[5] = q1.y; Pv[6] = q1.z; Pv[7] = q1.w;
                Pv[8] = q2.x; Pv[9] = q2.y;
                float hj = sh[r], h2j = sh2[r];
                float k0 = Krow[(size_t)(i0 + ty) * NP + j0 + r];
                float k1 = Krow[(size_t)(i0 + 16 + ty) * NP + j0 + r];
                float m0 = 0.f, m1 = 0.f;
                #pragma unroll
                for (int e = 0; e < EE; e++) {
                    m0 = fmaf(Treg[0][e], Pv[e], m0);
                    m1 = fmaf(Treg[1][e], Pv[e], m1);
                }
                float e0 = ex2f(m0), e1 = ex2f(m1);
                racc[0] = fmaf(e0, hj, racc[0]);
                racc[1] = fmaf(e1, hj, racc[1]);
                t2acc[0] = fmaf(e0 * h2j, k0, t2acc[0]);
                t2acc[1] = fmaf(e1 * h2j, k1, t2acc[1]);
            }
            __syncthreads();
        }

        #pragma unroll
        for (int ii = 0; ii < 2; ii++) {
            int r = ii * 16 + ty;
            acc = fmaf(sg[r], racc[ii], acc);
            tacc = fmaf(sg2[r], t2acc[ii], tacc);
        }
        __syncthreads();
    }

    float tot = blockReduceSum(acc, sred);
    float tt = blockReduceSum(tacc, sred);
    if (t == 0) {
        g_EDDd[c][b][a] = tot;
        g_trp[c][b][a] = tt;
    }
}

// ---------------- kernel 3: final assembly ---------------------------------
__global__ void __launch_bounds__(64)
k_final(const float* __restrict__ obs_mean, const float* __restrict__ obs_var,
        const float* __restrict__ alpha_sq, const float* __restrict__ sigma_sq_eps,
        float* __restrict__ out) {
    int b = blockIdx.x, t = threadIdx.x;
    if (t < DD) {
        out[b * DD + t] = obs_mean[b * DD + t] + g_mu_delta[b][t];
    }
    if (t < DD * DD) {
        int i = t / DD, j = t % DD;
        float edd;
        if (i == j) {
            edd = 0.f;
            #pragma unroll
            for (int c = 0; c < NCHUNK; c++) edd += g_EDDd[c][b][i];
        } else {
            edd = g_EDD[b][i][j];
        }
        float sd = edd - g_mu_delta[b][i] * g_mu_delta[b][j];
        if (i == j) {
            float tr = 0.f;
            #pragma unroll
            for (int c = 0; c < NCHUNK; c++) tr += g_trp[c][b][i];
            sd += alpha_sq[i] - tr + sigma_sq_eps[i];
        }
        float v = obs_var[b * DD * DD + i * DD + j] + sd + g_V[b][j][i] + g_V[b][i][j];
        out[BB * DD + b * DD * DD + i * DD + j] = v;
    }
}

extern "C" void kernel_launch(void* const* d_in, const int* in_sizes, int n_in,
                              void* d_out, int out_size) {
    const float* obs_mean     = (const float*)d_in[0];
    const float* obs_var      = (const float*)d_in[1];
    const float* action_mean  = (const float*)d_in[2];
    const float* action_var   = (const float*)d_in[3];
    const float* cross_cov    = (const float*)d_in[4];
    const float* X_train      = (const float*)d_in[5];
    const float* ell          = (const float*)d_in[6];
    const float* alpha_sq     = (const float*)d_in[7];
    const float* sigma_sq_eps = (const float*)d_in[8];
    const float* beta         = (const float*)d_in[9];
    const float* inv_K        = (const float*)d_in[10];
    float* out = (float*)d_out;

    k_solve<<<BB * NPAIR + BB * DD, 32>>>(obs_var, action_var, cross_cov, ell);
    k_emit<<<BB * NPAIR, NP>>>(obs_mean, obs_var, action_mean, action_var,
                               cross_cov, X_train, ell, alpha_sq, beta);
    k_main_off<<<BB * NOFF, 256>>>();
    k_main_diag<<<BB * DD * NCHUNK, 256>>>(inv_K);
    k_final<<<BB, 64>>>(obs_mean, obs_var, alpha_sq, sigma_sq_eps, out);
}

// round 16
// speedup vs baseline: 3.4986x; 1.0394x over previous
#include <cuda_runtime.h>
#include <math.h>

#define BB 16
#define DD 8
#define FF 2
#define EE 10
#define EP 12          // padded row (float4-aligned, 48B = 3x16B, odd multiple of 16)
#define NP 512
#define NPAIR 36
#define NOFF 28
#define NCHUNK 4       // i-chunk classes for the diagonal kernel (k mod NCHUNK)
#define LOG2E 1.4426950408889634f

// ---------------- scratch (device globals; no allocation allowed) ----------
__device__ float g_S[BB][NPAIR][EE][EE];     // S = R^{-1} Sigma
__device__ float g_ldR[BB][NPAIR];
__device__ float g_Ainv[BB][DD][EE][EE];
__device__ float g_ldA[BB][DD];
__device__ float g_Pp[BB][DD][NP][EP];       // padded P
__device__ float g_mu_delta[BB][DD];
__device__ float g_V[BB][DD][EE];
__device__ float g_Tlp[BB][NPAIR][NP][EP];   // (Pa @ S) * log2(e), padded
__device__ float g_gv[BB][NPAIR][NP];
__device__ float g_hv[BB][NPAIR][NP];
__device__ float g_g2[BB][NPAIR][NP];
__device__ float g_h2[BB][NPAIR][NP];
__device__ float g_EDD[BB][DD][DD];
__device__ float g_EDDd[NCHUNK][BB][DD];     // diag partials per chunk class
__device__ float g_trp[NCHUNK][BB][DD];      // trace partials per chunk class

__device__ __forceinline__ float ex2f(float x) {
    float y;
    asm("ex2.approx.ftz.f32 %0, %1;" : "=f"(y) : "f"(x));
    return y;
}

__device__ __forceinline__ void pair_of(int p, int &a, int &d) {
    int aa = 0;
    while (p >= DD - aa) { p -= DD - aa; aa++; }
    a = aa; d = aa + p;
}
__device__ __forceinline__ void pair_off(int p, int &a, int &d) {
    int aa = 0;
    while (p >= DD - 1 - aa) { p -= DD - 1 - aa; aa++; }
    a = aa; d = aa + 1 + p;
}
__device__ __forceinline__ int pfull(int a, int d) {
    return a * (2 * DD - a + 1) / 2 + (d - a);
}

__device__ float blockReduceSum(float v, float* sred) {
    const unsigned full = 0xffffffffu;
    #pragma unroll
    for (int o = 16; o > 0; o >>= 1) v += __shfl_down_sync(full, v, o);
    int t = threadIdx.x, warp = t >> 5, lane = t & 31;
    int nw = blockDim.x >> 5;
    if (lane == 0) sred[warp] = v;
    __syncthreads();
    float r = (t < nw) ? sred[t] : 0.f;
    if (warp == 0) {
        #pragma unroll
        for (int o = 16; o > 0; o >>= 1) r += __shfl_down_sync(full, r, o);
        if (lane == 0) sred[0] = r;
    }
    __syncthreads();
    float out = sred[0];
    __syncthreads();
    return out;
}

// Build Sigma[e][f] for batch b from the inputs.
__device__ __forceinline__ float sigma_elem(
    int b, int e, int f,
    const float* __restrict__ obs_var, const float* __restrict__ action_var,
    const float* __restrict__ cross_cov) {
    if (e < DD && f < DD)      return obs_var[b * DD * DD + e * DD + f];
    else if (e < DD)           return cross_cov[b * DD * FF + e * FF + (f - DD)];
    else if (f < DD)           return cross_cov[b * DD * FF + f * FF + (e - DD)];
    else                       return action_var[b * FF * FF + (e - DD) * FF + (f - DD)];
}

// ---------------- kernel 0: all 10x10 solves, one warp per solve -----------
__global__ void __launch_bounds__(32)
k_solve(const float* __restrict__ obs_var, const float* __restrict__ action_var,
        const float* __restrict__ cross_cov, const float* __restrict__ ell) {
    int bid = blockIdx.x;
    int lane = threadIdx.x;
    const bool isR = (bid < BB * NPAIR);

    __shared__ float W[EE][2 * EE];   // [M | X]
    __shared__ float sfac[EE];
    __shared__ float spinv;

    int b, a, d;
    if (isR) {
        b = bid / NPAIR;
        int p = bid % NPAIR;
        pair_of(p, a, d);
    } else {
        int idx = bid - BB * NPAIR;
        b = idx / DD;
        a = d = idx % DD;
    }

    for (int idx = lane; idx < EE * EE; idx += 32) {
        int e = idx / EE, f = idx % EE;
        float sig = sigma_elem(b, e, f, obs_var, action_var, cross_cov);
        if (isR) {
            float la = ell[a * EE + f], ld2 = ell[d * EE + f];
            float ils = 1.f / (la * la) + 1.f / (ld2 * ld2);
            W[e][f] = sig * ils + ((e == f) ? 1.f : 0.f);
            W[e][EE + f] = sig;
        } else {
            float l = ell[d * EE + e];
            W[e][f] = sig + ((e == f) ? (l * l) : 0.f);
            W[e][EE + f] = (e == f) ? 1.f : 0.f;
        }
    }
    __syncwarp();

    float ld = 0.f;
    for (int k = 0; k < EE; k++) {
        if (lane == 0) {
            float piv = W[k][k];
            ld += logf(fabsf(piv));
            spinv = 1.f / piv;
        }
        __syncwarp();
        if (lane < 2 * EE) W[k][lane] *= spinv;
        __syncwarp();
        if (lane < EE) sfac[lane] = (lane == k) ? 0.f : W[lane][k];
        __syncwarp();
        for (int idx = lane; idx < (EE - 1) * 2 * EE; idx += 32) {
            int rr = idx / (2 * EE), c = idx % (2 * EE);
            int r = rr + (rr >= k ? 1 : 0);
            W[r][c] -= sfac[r] * W[k][c];
        }
        __syncwarp();
    }

    if (isR) {
        int p = bid % NPAIR;
        for (int idx = lane; idx < EE * EE; idx += 32)
            g_S[b][p][idx / EE][idx % EE] = W[idx / EE][EE + idx % EE];
        if (lane == 0) g_ldR[b][p] = ld;
    } else {
        for (int idx = lane; idx < EE * EE; idx += 32)
            g_Ainv[b][d][idx / EE][idx % EE] = W[idx / EE][EE + idx % EE];
        if (lane == 0) g_ldA[b][d] = ld;
    }
}

// ---------------- kernel 1: emission per (b,pair), no GJ -------------------
__global__ void __launch_bounds__(NP)
k_emit(const float* __restrict__ obs_mean, const float* __restrict__ obs_var,
       const float* __restrict__ action_mean, const float* __restrict__ action_var,
       const float* __restrict__ cross_cov, const float* __restrict__ X_train,
       const float* __restrict__ ell, const float* __restrict__ alpha_sq,
       const float* __restrict__ beta) {
    int bp = blockIdx.x;
    int b = bp / NPAIR, p = bp % NPAIR;
    int a, d;
    pair_of(p, a, d);
    const bool diag = (a == d);
    int t = threadIdx.x;

    __shared__ float sX[EE][EE + 1];
    __shared__ float sSig[EE][EE + 1];
    __shared__ float smu[EE], siA[EE], siD[EE];
    __shared__ float slal2[2];
    __shared__ float sred[32];

    if (t < DD) smu[t] = obs_mean[b * DD + t];
    else if (t < EE) smu[t] = action_mean[b * FF + (t - DD)];
    if (t >= 32 && t < 32 + EE) {
        int e = t - 32; float l = ell[a * EE + e]; siA[e] = 1.f / (l * l);
    }
    if (t >= 64 && t < 64 + EE) {
        int e = t - 64; float l = ell[d * EE + e]; siD[e] = 1.f / (l * l);
    }
    if (t == 96) slal2[0] = logf(alpha_sq[a]);
    if (t == 97) slal2[1] = logf(alpha_sq[d]);
    if (t >= 128 && t < 128 + EE * EE) {
        int q = t - 128, e = q / EE, f = q % EE;
        sX[e][f] = g_S[b][p][e][f];
    }
    if (t >= 256 && t < 256 + EE * EE) {
        int q = t - 256, e = q / EE, f = q % EE;
        sSig[e][f] = sigma_elem(b, e, f, obs_var, action_var, cross_cov);
    }
    __syncthreads();

    float sld = g_ldR[b][p];

    int n = t;
    float nu[EE], Pa[EE], Pd[EE];
    float ka = slal2[0], kd = slal2[1];
    #pragma unroll
    for (int e = 0; e < EE; e++) {
        nu[e] = X_train[n * EE + e] - smu[e];
        Pa[e] = nu[e] * siA[e];
        Pd[e] = nu[e] * siD[e];
        ka -= 0.5f * nu[e] * Pa[e];
        kd -= 0.5f * nu[e] * Pd[e];
    }

    // a-side: T = Pa @ S, g
    {
        float Tv[EE];
        #pragma unroll
        for (int e = 0; e < EE; e++) {
            float acc = 0.f;
            #pragma unroll
            for (int f = 0; f < EE; f++) acc = fmaf(Pa[f], sX[f][e], acc);
            Tv[e] = acc;
        }
        float da = 0.f;
        #pragma unroll
        for (int e = 0; e < EE; e++) da = fmaf(Tv[e], Pa[e], da);
        #pragma unroll
        for (int e = 0; e < EE; e++) g_Tlp[b][p][n][e] = Tv[e] * LOG2E;
        g_Tlp[b][p][n][10] = 0.f;
        g_Tlp[b][p][n][11] = 0.f;
        float g2 = __expf(ka + 0.5f * da - 0.25f * sld);
        g_g2[b][p][n] = g2;
        g_gv[b][p][n] = beta[a * NP + n] * g2;
    }
    // d-side: h
    {
        float Tv[EE];
        #pragma unroll
        for (int e = 0; e < EE; e++) {
            float acc = 0.f;
            #pragma unroll
            for (int f = 0; f < EE; f++) acc = fmaf(Pd[f], sX[f][e], acc);
            Tv[e] = acc;
        }
        float db = 0.f;
        #pragma unroll
        for (int e = 0; e < EE; e++) db = fmaf(Tv[e], Pd[e], db);
        float h2 = __expf(kd + 0.5f * db - 0.25f * sld);
        g_h2[b][p][n] = h2;
        g_hv[b][p][n] = beta[d * NP + n] * h2;
    }

    if (diag) {
        #pragma unroll
        for (int e = 0; e < EE; e++) g_Pp[b][d][n][e] = Pd[e];
        g_Pp[b][d][n][10] = 0.f;
        g_Pp[b][d][n][11] = 0.f;

        __syncthreads();
        if (t >= 128 && t < 128 + EE * EE) {
            int q = t - 128, e = q / EE, f = q % EE;
            sX[e][f] = g_Ainv[b][d][e][f];
        }
        __syncthreads();
        float sldA = g_ldA[b][d];

        float ldl = 0.f;
        #pragma unroll
        for (int e = 0; e < EE; e++) ldl -= logf(siD[e]);

        float quad = 0.f;
        #pragma unroll
        for (int e = 0; e < EE; e++) {
            float acc = 0.f;
            #pragma unroll
            for (int f = 0; f < EE; f++) acc = fmaf(sX[e][f], nu[f], acc);
            quad = fmaf(nu[e], acc, quad);
        }
        float q = alpha_sq[d] * __expf(0.5f * (ldl - sldA) - 0.5f * quad);
        float bq = beta[d * NP + n] * q;

        float md = blockReduceSum(bq, sred);
        float wreg[EE];
        for (int e = 0; e < EE; e++) wreg[e] = blockReduceSum(bq * nu[e], sred);

        if (t == 0) {
            g_mu_delta[b][d] = md;
            float u[EE];
            for (int e = 0; e < EE; e++) {
                float acc = 0.f;
                for (int f = 0; f < EE; f++) acc = fmaf(sX[e][f], wreg[f], acc);
                u[e] = acc;
            }
            for (int e = 0; e < EE; e++) {
                float acc = 0.f;
                for (int f = 0; f < EE; f++) acc = fmaf(sSig[e][f], u[f], acc);
                g_V[b][d][e] = acc;
            }
        }
    }
}

// ---------------- kernel 2a: off-diagonal pairs (a<d) ----------------------
// At the FMA roofline; unchanged.
__global__ void __launch_bounds__(256, 3) k_main_off() {
    int bp = blockIdx.x;
    int b = bp / NOFF, p28 = bp % NOFF;
    int a, d;
    pair_off(p28, a, d);
    int p = pfull(a, d);
    int t = threadIdx.x, tx = t & 15, ty = t >> 4;

    __shared__ __align__(16) float sT[64][EP];
    __shared__ __align__(16) float sP[64][EP];
    __shared__ float sg[64], sh[64];
    __shared__ float sred[32];

    float acc = 0.f;

    for (int i0 = 0; i0 < NP; i0 += 64) {
        {
            const float4* srcT = (const float4*)&g_Tlp[b][p][i0][0];
            float4* dstT = (float4*)&sT[0][0];
            for (int k = t; k < 64 * EP / 4; k += 256) dstT[k] = srcT[k];
            if (t < 64) sg[t] = g_gv[b][p][i0 + t];
        }
        __syncthreads();

        float Treg[4][EE];
        #pragma unroll
        for (int ii = 0; ii < 4; ii++) {
            int r = ii * 16 + ty;
            const float4 w0 = *(const float4*)&sT[r][0];
            const float4 w1 = *(const float4*)&sT[r][4];
            const float2 w2 = *(const float2*)&sT[r][8];
            Treg[ii][0] = w0.x; Treg[ii][1] = w0.y; Treg[ii][2] = w0.z; Treg[ii][3] = w0.w;
            Treg[ii][4] = w1.x; Treg[ii][5] = w1.y; Treg[ii][6] = w1.z; Treg[ii][7] = w1.w;
            Treg[ii][8] = w2.x; Treg[ii][9] = w2.y;
        }

        float racc[4] = {0.f, 0.f, 0.f, 0.f};

        for (int j0 = 0; j0 < NP; j0 += 64) {
            {
                const float4* srcP = (const float4*)&g_Pp[b][d][j0][0];
                float4* dstP = (float4*)&sP[0][0];
                for (int k = t; k < 64 * EP / 4; k += 256) dstP[k] = srcP[k];
                if (t < 64) sh[t] = g_hv[b][p][j0 + t];
            }
            __syncthreads();

            #pragma unroll
            for (int jj = 0; jj < 4; jj++) {
                int r = jj * 16 + tx;
                const float4 q0 = *(const float4*)&sP[r][0];
                const float4 q1 = *(const float4*)&sP[r][4];
                const float2 q2 = *(const float2*)&sP[r][8];
                float Pv[EE];
                Pv[0] = q0.x; Pv[1] = q0.y; Pv[2] = q0.z; Pv[3] = q0.w;
                Pv[4] = q1.x; Pv[5] = q1.y; Pv[6] = q1.z; Pv[7] = q1.w;
                Pv[8] = q2.x; Pv[9] = q2.y;
                float hj = sh[r];
                float m0 = 0.f, m1 = 0.f, m2 = 0.f, m3 = 0.f;
                #pragma unroll
                for (int e = 0; e < EE; e++) {
                    m0 = fmaf(Treg[0][e], Pv[e], m0);
                    m1 = fmaf(Treg[1][e], Pv[e], m1);
                    m2 = fmaf(Treg[2][e], Pv[e], m2);
                    m3 = fmaf(Treg[3][e], Pv[e], m3);
                }
                racc[0] = fmaf(ex2f(m0), hj, racc[0]);
                racc[1] = fmaf(ex2f(m1), hj, racc[1]);
                racc[2] = fmaf(ex2f(m2), hj, racc[2]);
                racc[3] = fmaf(ex2f(m3), hj, racc[3]);
            }
            __syncthreads();
        }

        #pragma unroll
        for (int ii = 0; ii < 4; ii++) acc = fmaf(sg[ii * 16 + ty], racc[ii], acc);
        __syncthreads();
    }

    float tot = blockReduceSum(acc, sred);
    if (t == 0) {
        g_EDD[b][a][d] = tot;
        g_EDD[b][d][a] = tot;
    }
}

// ---------------- kernel 2b: diagonal pairs (a==d), symmetric-half ---------
// For a==d: m_ij is symmetric, g==h, invK symmetric. Process only j-tiles
// at/above the diagonal; w=2 above, per-element 2/1/0 on the straddle tile.
// invK tiles staged in smem (padded row 68 -> conflict-free reads).
__global__ void __launch_bounds__(256, 3) k_main_diag(const float* __restrict__ invK) {
    int bp = blockIdx.x;
    int c = bp & (NCHUNK - 1);
    int ba = bp >> 2;
    int b = ba / DD, a = ba % DD;
    int p = pfull(a, a);
    int t = threadIdx.x, tx = t & 15, ty = t >> 4;

    __shared__ __align__(16) float sT[32][EP];
    __shared__ __align__(16) float sP[64][EP];
    __shared__ __align__(16) float sK[32][68];
    __shared__ float sg[32], sh[64], sg2[32], sh2[64];
    __shared__ float sred[32];

    const float* Krow = invK + (size_t)a * NP * NP;

    float acc = 0.f, tacc = 0.f;

    // i-tiles k = c, c+NCHUNK, ... (mod-NCHUNK striding balances triangular work)
    for (int k = c; k < NP / 32; k += NCHUNK) {
        const int i0 = k * 32;
        {
            const float4* srcT = (const float4*)&g_Tlp[b][p][i0][0];
            float4* dstT = (float4*)&sT[0][0];
            for (int q = t; q < 32 * EP / 4; q += 256) dstT[q] = srcT[q];
            if (t < 32) {
                sg[t] = g_gv[b][p][i0 + t];
                sg2[t] = g_g2[b][p][i0 + t];
            }
        }
        __syncthreads();

        float Treg[2][EE];
        #pragma unroll
        for (int ii = 0; ii < 2; ii++) {
            int r = ii * 16 + ty;
            const float4 w0 = *(const float4*)&sT[r][0];
            const float4 w1 = *(const float4*)&sT[r][4];
            const float2 w2 = *(const float2*)&sT[r][8];
            Treg[ii][0] = w0.x; Treg[ii][1] = w0.y; Treg[ii][2] = w0.z; Treg[ii][3] = w0.w;
            Treg[ii][4] = w1.x; Treg[ii][5] = w1.y; Treg[ii][6] = w1.z; Treg[ii][7] = w1.w;
            Treg[ii][8] = w2.x; Treg[ii][9] = w2.y;
        }

        float racc[2] = {0.f, 0.f};
        float t2acc[2] = {0.f, 0.f};

        const int ig0 = i0 + ty;         // global i of row 0
        const int ig1 = i0 + 16 + ty;    // global i of row 1
        const int mstart = k >> 1;       // first j-tile touching/above diagonal

        for (int m = mstart; m < NP / 64; m++) {
            const int j0 = m * 64;
            {
                const float4* srcP = (const float4*)&g_Pp[b][a][j0][0];
                float4* dstP = (float4*)&sP[0][0];
                for (int q = t; q < 64 * EP / 4; q += 256) dstP[q] = srcP[q];
                if (t < 64) {
                    sh[t] = g_hv[b][p][j0 + t];
                    sh2[t] = g_h2[b][p][j0 + t];
                }
                // stage invK tile [32 x 64] -> sK
                for (int q = t; q < 32 * 64 / 4; q += 256) {
                    int row = q >> 4, c4 = q & 15;
                    const float4 kv = *(const float4*)(Krow + (size_t)(i0 + row) * NP + j0 + c4 * 4);
                    *(float4*)&sK[row][c4 * 4] = kv;
                }
            }
            __syncthreads();

            const bool straddle = (m == mstart) && (j0 <= i0 + 31);

            #pragma unroll
            for (int jj = 0; jj < 4; jj++) {
                int r = jj * 16 + tx;
                const float4 q0 = *(const float4*)&sP[r][0];
                const float4 q1 = *(const float4*)&sP[r][4];
                const float2 q2 = *(const float2*)&sP[r][8];
                float Pv[EE];
                Pv[0] = q0.x; Pv[1] = q0.y; Pv[2] = q0.z; Pv[3] = q0.w;
                Pv[4] = q1.x; Pv[5] = q1.y; Pv[6] = q1.z; Pv[7] = q1.w;
                Pv[8] = q2.x; Pv[9] = q2.y;
                float hj = sh[r], h2j = sh2[r];
                float k0 = sK[ty][r];
                float k1 = sK[16 + ty][r];
                float m0 = 0.f, m1 = 0.f;
                #pragma unroll
                for (int e = 0; e < EE; e++) {
                    m0 = fmaf(Treg[0][e], Pv[e], m0);
                    m1 = fmaf(Treg[1][e], Pv[e], m1);
                }
                float e0 = ex2f(m0), e1 = ex2f(m1);
                float w0 = 2.f, w1 = 2.f;
                if (straddle) {
                    int jg = j0 + r;
                    w0 = (jg > ig0) ? 2.f : ((jg == ig0) ? 1.f : 0.f);
                    w1 = (jg > ig1) ? 2.f : ((jg == ig1) ? 1.f : 0.f);
                }
                e0 *= w0; e1 *= w1;
                racc[0] = fmaf(e0, hj, racc[0]);
                racc[1] = fmaf(e1, hj, racc[1]);
                t2acc[0] = fmaf(e0 * h2j, k0, t2acc[0]);
                t2acc[1] = fmaf(e1 * h2j, k1, t2acc[1]);
            }
            __syncthreads();
        }

        #pragma unroll
        for (int ii = 0; ii < 2; ii++) {
            int r = ii * 16 + ty;
            acc = fmaf(sg[r], racc[ii], acc);
            tacc = fmaf(sg2[r], t2acc[ii], tacc);
        }
        __syncthreads();
    }

    float tot = blockReduceSum(acc, sred);
    float tt = blockReduceSum(tacc, sred);
    if (t == 0) {
        g_EDDd[c][b][a] = tot;
        g_trp[c][b][a] = tt;
    }
}

// ---------------- kernel 3: final assembly ---------------------------------
__global__ void __launch_bounds__(64)
k_final(const float* __restrict__ obs_mean, const float* __restrict__ obs_var,
        const float* __restrict__ alpha_sq, const float* __restrict__ sigma_sq_eps,
        float* __restrict__ out) {
    int b = blockIdx.x, t = threadIdx.x;
    if (t < DD) {
        out[b * DD + t] = obs_mean[b * DD + t] + g_mu_delta[b][t];
    }
    if (t < DD * DD) {
        int i = t / DD, j = t % DD;
        float edd;
        if (i == j) {
            edd = 0.f;
            #pragma unroll
            for (int c = 0; c < NCHUNK; c++) edd += g_EDDd[c][b][i];
        } else {
            edd = g_EDD[b][i][j];
        }
        float sd = edd - g_mu_delta[b][i] * g_mu_delta[b][j];
        if (i == j) {
            float tr = 0.f;
            #pragma unroll
            for (int c = 0; c < NCHUNK; c++) tr += g_trp[c][b][i];
            sd += alpha_sq[i] - tr + sigma_sq_eps[i];
        }
        float v = obs_var[b * DD * DD + i * DD + j] + sd + g_V[b][j][i] + g_V[b][i][j];
        out[BB * DD + b * DD * DD + i * DD + j] = v;
    }
}

extern "C" void kernel_launch(void* const* d_in, const int* in_sizes, int n_in,
                              void* d_out, int out_size) {
    const float* obs_mean     = (const float*)d_in[0];
    const float* obs_var      = (const float*)d_in[1];
    const float* action_mean  = (const float*)d_in[2];
    const float* action_var   = (const float*)d_in[3];
    const float* cross_cov    = (const float*)d_in[4];
    const float* X_train      = (const float*)d_in[5];
    const float* ell          = (const float*)d_in[6];
    const float* alpha_sq     = (const float*)d_in[7];
    const float* sigma_sq_eps = (const float*)d_in[8];
    const float* beta         = (const float*)d_in[9];
    const float* inv_K        = (const float*)d_in[10];
    float* out = (float*)d_out;

    k_solve<<<BB * NPAIR + BB * DD, 32>>>(obs_var, action_var, cross_cov, ell);
    k_emit<<<BB * NPAIR, NP>>>(obs_mean, obs_var, action_mean, action_var,
                               cross_cov, X_train, ell, alpha_sq, beta);
    k_main_off<<<BB * NOFF, 256>>>();
    k_main_diag<<<BB * DD * NCHUNK, 256>>>(inv_K);
    k_final<<<BB, 64>>>(obs_mean, obs_var, alpha_sq, sigma_sq_eps, out);
}